// round 13
// baseline (speedup 1.0000x reference)
#include <cuda_runtime.h>
#include <cuda_bf16.h>
#include <math.h>
#include <stdint.h>

#define N_NODES 50000
#define E_EDGES 800000
#define F_INPUT 128
#define HDIM    256
#define C_OUT   112
#define L_LAYERS 8
#define BN_EPS  1e-5f

// ---------------- scratch (device globals; no allocations anywhere) --------
__device__ float g_h0[N_NODES * HDIM];                       // input FC output
__device__ float g_t[N_NODES * HDIM];                        // t' per layer
__device__ float g_hist[L_LAYERS * N_NODES * HDIM];          // raw agg out per layer
__device__ __nv_bfloat16 g_wth[L_LAYERS * HDIM * HDIM];      // convW^T hi [l][n][k]
__device__ __nv_bfloat16 g_wtl[L_LAYERS * HDIM * HDIM];      // convW^T lo
__device__ __nv_bfloat16 g_inwh[HDIM * F_INPUT];             // in_W^T hi [n][k]
__device__ __nv_bfloat16 g_inwl[HDIM * F_INPUT];             // in_W^T lo
__device__ float g_dinv1[N_NODES];
__device__ float g_dinv2[N_NODES];
__device__ float g_sums[L_LAYERS * HDIM];
__device__ float g_sqs[L_LAYERS * HDIM];
__device__ float g_w[L_LAYERS];
__device__ int g_cnt1[N_NODES];
__device__ int g_cnt2[N_NODES];
__device__ int g_rp1[N_NODES + 1];
__device__ int g_rp2[N_NODES + 1];
__device__ int g_cur1[N_NODES];
__device__ int g_cur2[N_NODES];
__device__ int g_csr1[E_EDGES];
__device__ int g_csr2[E_EDGES];

// ---------------- helpers ---------------------------------------------------
__device__ __forceinline__ uint32_t smem_u32(const void* p) {
    uint32_t a;
    asm("{ .reg .u64 t; cvta.to.shared.u64 t, %1; cvt.u32.u64 %0, t; }"
        : "=r"(a) : "l"(p));
    return a;
}
__device__ __forceinline__ unsigned long long pk2(float lo, float hi) {
    unsigned long long r;
    asm("mov.b64 %0, {%1, %2};" : "=l"(r) : "f"(lo), "f"(hi));
    return r;
}
__device__ __forceinline__ void upk2(float& lo, float& hi, unsigned long long v) {
    asm("mov.b64 {%0, %1}, %2;" : "=f"(lo), "=f"(hi) : "l"(v));
}
__device__ __forceinline__ void ffma2(unsigned long long& d,
                                      unsigned long long a, unsigned long long b) {
    asm("fma.rn.f32x2 %0, %1, %2, %0;" : "+l"(d) : "l"(a), "l"(b));
}
__device__ __forceinline__ void ldm_x4(uint32_t& r0, uint32_t& r1,
                                       uint32_t& r2, uint32_t& r3, uint32_t addr) {
    asm volatile("ldmatrix.sync.aligned.m8n8.x4.shared.b16 {%0,%1,%2,%3}, [%4];"
                 : "=r"(r0), "=r"(r1), "=r"(r2), "=r"(r3) : "r"(addr));
}
__device__ __forceinline__ void mma_bf16(float* d, const uint32_t* a,
                                         uint32_t b0, uint32_t b1) {
    asm volatile(
        "mma.sync.aligned.m16n8k16.row.col.f32.bf16.bf16.f32 "
        "{%0,%1,%2,%3}, {%4,%5,%6,%7}, {%8,%9}, {%0,%1,%2,%3};"
        : "+f"(d[0]), "+f"(d[1]), "+f"(d[2]), "+f"(d[3])
        : "r"(a[0]), "r"(a[1]), "r"(a[2]), "r"(a[3]), "r"(b0), "r"(b1));
}
__device__ __forceinline__ void cpa16(uint32_t dst, const void* src) {
    asm volatile("cp.async.cg.shared.global [%0], [%1], 16;"
                 :: "r"(dst), "l"(src));
}
__device__ __forceinline__ uint32_t bf2pack(__nv_bfloat16 a, __nv_bfloat16 b) {
    __nv_bfloat162 p = {a, b};
    return *(uint32_t*)&p;
}

// ---------------- prep: weight splits + zero stats/cnts + softmax(w) --------
__global__ void prep_kernel(const float* __restrict__ convW,
                            const float* __restrict__ in_W,
                            const float* __restrict__ lw,
                            __nv_bfloat16* wth, __nv_bfloat16* wtl,
                            __nv_bfloat16* inwh, __nv_bfloat16* inwl,
                            float* sums, float* sqs, float* w,
                            int* cnt1, int* cnt2) {
    int i = blockIdx.x * blockDim.x + threadIdx.x;
    if (i < L_LAYERS * HDIM) { sums[i] = 0.f; sqs[i] = 0.f; }
    if (i < N_NODES) { cnt1[i] = 0; cnt2[i] = 0; }
    if (i == 0) {
        float m = -1e30f;
        for (int l = 0; l < L_LAYERS; l++) m = fmaxf(m, lw[l]);
        float s = 0.f;
        for (int l = 0; l < L_LAYERS; l++) s += expf(lw[l] - m);
        for (int l = 0; l < L_LAYERS; l++) w[l] = expf(lw[l] - m) / s;
    }
    if (i < HDIM * F_INPUT) {   // in_W^T split: [n=256][k=128]
        int n = i / F_INPUT;
        int k = i % F_INPUT;
        float v = in_W[k * HDIM + n];
        __nv_bfloat16 hi = __float2bfloat16(v);
        inwh[i] = hi;
        inwl[i] = __float2bfloat16(v - __bfloat162float(hi));
    }
    if (i >= L_LAYERS * HDIM * HDIM) return;
    int l = i >> 16;
    int n = (i >> 8) & 255;
    int k = i & 255;
    float v = convW[(l << 16) + (k << 8) + n];
    __nv_bfloat16 hi = __float2bfloat16(v);
    wth[i] = hi;
    wtl[i] = __float2bfloat16(v - __bfloat162float(hi));
}

// ---------------- CSR build (both adjacencies per launch) -------------------
__global__ void hist2_kernel(const int* __restrict__ t1, const int* __restrict__ t2,
                             int* c1, int* c2) {
    int i = blockIdx.x * blockDim.x + threadIdx.x;
    if (i < E_EDGES) {
        atomicAdd(&c1[t1[i]], 1);
        atomicAdd(&c2[t2[i]], 1);
    }
}

// single-block scan per adjacency (block 0 -> adj1, block 1 -> adj2),
// warp-shuffle hierarchy, fused dinv + cursor emission.
__global__ void scan2_kernel(const int* __restrict__ c1, const int* __restrict__ c2,
                             int* r1, int* r2,
                             float* d1, float* d2, int* cu1, int* cu2) {
    __shared__ int wsum[32];
    const int* cnt = blockIdx.x ? c2 : c1;
    int* rowptr    = blockIdx.x ? r2 : r1;
    float* dinv    = blockIdx.x ? d2 : d1;
    int* cur       = blockIdx.x ? cu2 : cu1;
    const int T = 1024;
    const int CH = 52;                 // multiple of 4; 52*1024 >= N_NODES
    int t = threadIdx.x;
    int lane = t & 31;
    int wid = t >> 5;
    int base = t * CH;
    int loc = 0;
#pragma unroll 4
    for (int i = 0; i < CH; i += 4) {
        int idx = base + i;
        if (idx + 3 < N_NODES) {
            int4 v = *(const int4*)(cnt + idx);
            loc += v.x + v.y + v.z + v.w;
        } else {
#pragma unroll
            for (int j = 0; j < 4; j++)
                if (idx + j < N_NODES) loc += cnt[idx + j];
        }
    }
    // warp inclusive scan
    int v = loc;
#pragma unroll
    for (int off = 1; off < 32; off <<= 1) {
        int n = __shfl_up_sync(0xffffffffu, v, off);
        if (lane >= off) v += n;
    }
    if (lane == 31) wsum[wid] = v;
    __syncthreads();
    if (wid == 0) {
        int wv = wsum[lane];
#pragma unroll
        for (int off = 1; off < 32; off <<= 1) {
            int n = __shfl_up_sync(0xffffffffu, wv, off);
            if (lane >= off) wv += n;
        }
        wsum[lane] = wv;
    }
    __syncthreads();
    int run = v - loc + (wid > 0 ? wsum[wid - 1] : 0);   // exclusive prefix
#pragma unroll 4
    for (int i = 0; i < CH; i += 4) {
        int idx = base + i;
        if (idx + 3 < N_NODES) {
            int4 c = *(const int4*)(cnt + idx);
            int4 o;
            float4 dv;
            o.x = run; dv.x = rsqrtf((float)c.x + 1.0f); run += c.x;
            o.y = run; dv.y = rsqrtf((float)c.y + 1.0f); run += c.y;
            o.z = run; dv.z = rsqrtf((float)c.z + 1.0f); run += c.z;
            o.w = run; dv.w = rsqrtf((float)c.w + 1.0f); run += c.w;
            *(int4*)(rowptr + idx) = o;
            *(int4*)(cur + idx)    = o;
            *(float4*)(dinv + idx) = dv;
        } else {
#pragma unroll
            for (int j = 0; j < 4; j++)
                if (idx + j < N_NODES) {
                    int c = cnt[idx + j];
                    rowptr[idx + j] = run;
                    cur[idx + j]    = run;
                    dinv[idx + j]   = rsqrtf((float)c + 1.0f);
                    run += c;
                }
        }
    }
    if (t == T - 1) rowptr[N_NODES] = run;
}

__global__ void fill2_kernel(const int* __restrict__ e1, const int* __restrict__ e2,
                             int* cu1, int* cu2, int* cs1, int* cs2) {
    int i = blockIdx.x * blockDim.x + threadIdx.x;
    if (i < E_EDGES) {
        int p1 = atomicAdd(&cu1[e1[E_EDGES + i]], 1);
        cs1[p1] = e1[i];
        int p2 = atomicAdd(&cu2[e2[E_EDGES + i]], 1);
        cs2[p2] = e2[i];
    }
}

// ---------------- mma.sync GEMM, fused BN+ReLU+bf16-split A-staging --------
// C[M,256] = bf16split(relu?(bn?(Hin[M,K]))) @ B^T + bias, opt * dinv.
// CTA 128x128, warp 32x64, K chunk 32 (K = 128 or 256), double-buffered.
#define SROW 40
#define ABUF (128 * SROW * 2)                 // 10240 B per array per buffer
#define MG_SMEM (8 * ABUF + 2048)             // + bn param tables

__global__ __launch_bounds__(256, 2)
void mma_gemm_kernel(const float* __restrict__ Hin, int K,
                     const float* __restrict__ bsum, const float* __restrict__ bsq,
                     const float* __restrict__ gamma, const float* __restrict__ beta,
                     int do_bn,
                     const __nv_bfloat16* __restrict__ Bh,
                     const __nv_bfloat16* __restrict__ Bl,
                     const float* __restrict__ bias,
                     const float* __restrict__ dinv,
                     float* __restrict__ C, int M) {
    extern __shared__ char dsm[];
    float* sS  = (float*)(dsm + 8 * ABUF);
    float* sSh = sS + 256;
    const uint32_t sb = smem_u32(dsm);
    const int tid  = threadIdx.x;
    const int lane = tid & 31;
    const int wid  = tid >> 5;
    const int wm   = wid & 3;
    const int wn   = wid >> 2;
    const int brow = blockIdx.y * 128;
    const int bcol = blockIdx.x * 128;
    const int nch  = K >> 5;

    if (tid < 256) {
        if (do_bn) {
            float mu  = bsum[tid] * (1.0f / N_NODES);
            float var = bsq[tid] * (1.0f / N_NODES) - mu * mu;
            float s = gamma[tid] * rsqrtf(var + BN_EPS);
            sS[tid] = s;
            sSh[tid] = beta[tid] - mu * s;
        } else {
            sS[tid] = 1.f;
            sSh[tid] = 0.f;
        }
    }

    const int r0 = tid >> 2, r1 = r0 + 64, sg = tid & 3;
    const int gr0 = min(brow + r0, M - 1);
    const int gr1 = min(brow + r1, M - 1);
    const int wn0 = bcol + r0, wn1 = bcol + r1;
    const uint32_t d0 = (uint32_t)(r0 * SROW + sg * 8) * 2;
    const uint32_t d1 = (uint32_t)(r1 * SROW + sg * 8) * 2;

    auto issueB = [&](int c) {
        const int kb = c * 32 + sg * 8;
        const uint32_t bo = (uint32_t)(c & 1) * ABUF;
        cpa16(sb + 4 * ABUF + bo + d0, Bh + (size_t)wn0 * K + kb);
        cpa16(sb + 4 * ABUF + bo + d1, Bh + (size_t)wn1 * K + kb);
        cpa16(sb + 6 * ABUF + bo + d0, Bl + (size_t)wn0 * K + kb);
        cpa16(sb + 6 * ABUF + bo + d1, Bl + (size_t)wn1 * K + kb);
        asm volatile("cp.async.commit_group;");
    };

    float4 ar[4];
    auto loadA = [&](int c) {
        const int kb = c * 32 + sg * 8;
        ar[0] = *(const float4*)(Hin + (size_t)gr0 * K + kb);
        ar[1] = *(const float4*)(Hin + (size_t)gr0 * K + kb + 4);
        ar[2] = *(const float4*)(Hin + (size_t)gr1 * K + kb);
        ar[3] = *(const float4*)(Hin + (size_t)gr1 * K + kb + 4);
    };
    auto stageA = [&](int c) {
        const int kb = c * 32 + sg * 8;
        const uint32_t bo = (uint32_t)(c & 1) * ABUF;
        float s[8], sh[8];
#pragma unroll
        for (int j = 0; j < 8; j++) { s[j] = sS[kb + j]; sh[j] = sSh[kb + j]; }
        const float* av = (const float*)ar;
        uint32_t hiw[4], low[4];
#pragma unroll
        for (int rr = 0; rr < 2; rr++) {
            __nv_bfloat16 hb[8], lb[8];
#pragma unroll
            for (int j = 0; j < 8; j++) {
                float v = fmaf(av[rr * 8 + j], s[j], sh[j]);
                if (do_bn) v = fmaxf(v, 0.f);
                hb[j] = __float2bfloat16(v);
                lb[j] = __float2bfloat16(v - __bfloat162float(hb[j]));
            }
#pragma unroll
            for (int j = 0; j < 4; j++) {
                hiw[j] = bf2pack(hb[2 * j], hb[2 * j + 1]);
                low[j] = bf2pack(lb[2 * j], lb[2 * j + 1]);
            }
            const uint32_t dd = rr ? d1 : d0;
            *(uint4*)(dsm + bo + dd)            = *(uint4*)hiw;
            *(uint4*)(dsm + 2 * ABUF + bo + dd) = *(uint4*)low;
        }
    };

    // ldmatrix lane offsets
    const int li = lane & 7;
    const int lb_ = (lane >> 3) & 1;
    const int lc = (lane >> 4) & 1;
    uint32_t aoff[2], boff[4];
#pragma unroll
    for (int mf = 0; mf < 2; mf++)
        aoff[mf] = (uint32_t)((wm * 32 + mf * 16 + lb_ * 8 + li) * SROW + lc * 8) * 2;
#pragma unroll
    for (int nf = 0; nf < 4; nf++)
        boff[nf] = (uint32_t)((wn * 64 + nf * 16 + lc * 8 + li) * SROW + lb_ * 8) * 2;

    float acc[2][8][4];
#pragma unroll
    for (int i = 0; i < 2; i++)
#pragma unroll
        for (int j = 0; j < 8; j++)
#pragma unroll
            for (int k = 0; k < 4; k++) acc[i][j][k] = 0.f;

    issueB(0);
    loadA(0);
    __syncthreads();        // sS/sSh ready
    stageA(0);

    for (int c = 0; c < nch; c++) {
        asm volatile("cp.async.wait_group 0;" ::: "memory");
        __syncthreads();    // A(c)+B(c) visible; all MMA(c-1) reads done
        if (c + 1 < nch) { issueB(c + 1); loadA(c + 1); }

        const uint32_t bo  = (uint32_t)(c & 1) * ABUF;
        const uint32_t bAh = sb + bo;
        const uint32_t bAl = sb + 2 * ABUF + bo;
        const uint32_t bBh = sb + 4 * ABUF + bo;
        const uint32_t bBl = sb + 6 * ABUF + bo;
#pragma unroll
        for (int ks = 0; ks < 2; ks++) {
            const uint32_t kadd = ks * 32;
            uint32_t A0h[4], A1h[4], A0l[4], A1l[4];
            ldm_x4(A0h[0], A0h[1], A0h[2], A0h[3], bAh + aoff[0] + kadd);
            ldm_x4(A1h[0], A1h[1], A1h[2], A1h[3], bAh + aoff[1] + kadd);
            ldm_x4(A0l[0], A0l[1], A0l[2], A0l[3], bAl + aoff[0] + kadd);
            ldm_x4(A1l[0], A1l[1], A1l[2], A1l[3], bAl + aoff[1] + kadd);
#pragma unroll
            for (int nf = 0; nf < 4; nf++) {
                uint32_t bh[4], bl[4];
                ldm_x4(bh[0], bh[1], bh[2], bh[3], bBh + boff[nf] + kadd);
                ldm_x4(bl[0], bl[1], bl[2], bl[3], bBl + boff[nf] + kadd);
                mma_bf16(acc[0][nf * 2 + 0], A0h, bh[0], bh[1]);
                mma_bf16(acc[0][nf * 2 + 0], A0h, bl[0], bl[1]);
                mma_bf16(acc[0][nf * 2 + 0], A0l, bh[0], bh[1]);
                mma_bf16(acc[0][nf * 2 + 1], A0h, bh[2], bh[3]);
                mma_bf16(acc[0][nf * 2 + 1], A0h, bl[2], bl[3]);
                mma_bf16(acc[0][nf * 2 + 1], A0l, bh[2], bh[3]);
                mma_bf16(acc[1][nf * 2 + 0], A1h, bh[0], bh[1]);
                mma_bf16(acc[1][nf * 2 + 0], A1h, bl[0], bl[1]);
                mma_bf16(acc[1][nf * 2 + 0], A1l, bh[0], bh[1]);
                mma_bf16(acc[1][nf * 2 + 1], A1h, bh[2], bh[3]);
                mma_bf16(acc[1][nf * 2 + 1], A1h, bl[2], bl[3]);
                mma_bf16(acc[1][nf * 2 + 1], A1l, bh[2], bh[3]);
            }
        }
        if (c + 1 < nch) stageA(c + 1);
    }

    // epilogue: C[r, c] = (acc + bias[c]) * (dinv ? dinv[r] : 1)
    const int qr = lane >> 2;
    const int qc = (lane & 3) * 2;
#pragma unroll
    for (int mf = 0; mf < 2; mf++) {
        int rr0 = brow + wm * 32 + mf * 16 + qr;
        int rr1 = rr0 + 8;
        float dv0 = (rr0 < M) ? (dinv ? dinv[rr0] : 1.0f) : 0.f;
        float dv1 = (rr1 < M) ? (dinv ? dinv[rr1] : 1.0f) : 0.f;
#pragma unroll
        for (int nf = 0; nf < 8; nf++) {
            int cc = bcol + wn * 64 + nf * 8 + qc;
            float b0 = bias[cc], b1 = bias[cc + 1];
            if (rr0 < M)
                *(float2*)(C + (size_t)rr0 * HDIM + cc) =
                    make_float2((acc[mf][nf][0] + b0) * dv0,
                                (acc[mf][nf][1] + b1) * dv0);
            if (rr1 < M)
                *(float2*)(C + (size_t)rr1 * HDIM + cc) =
                    make_float2((acc[mf][nf][2] + b0) * dv1,
                                (acc[mf][nf][3] + b1) * dv1);
        }
    }
}

// ---------------- CSR aggregation + fused BN stats ---------------------------
__global__ __launch_bounds__(256)
void agg_kernel(const int* __restrict__ rowptr, const int* __restrict__ csr,
                const float* __restrict__ dinv, const float* __restrict__ tp,
                float* __restrict__ h, float* gsum, float* gsq) {
    __shared__ float s_sum[HDIM];
    __shared__ float s_sq[HDIM];
    int tid  = threadIdx.x;
    int lane = tid & 31;
    int warp = tid >> 5;
    int gw   = blockIdx.x * 8 + warp;
    int nw   = gridDim.x * 8;

    s_sum[tid] = 0.f;
    s_sq[tid]  = 0.f;

    float ssum[8], ssq[8];
#pragma unroll
    for (int i = 0; i < 8; i++) { ssum[i] = 0.f; ssq[i] = 0.f; }

    for (int v = gw; v < N_NODES; v += nw) {
        const float4* self = (const float4*)(tp + (size_t)v * HDIM);
        float4 a0 = self[lane];
        float4 a1 = self[lane + 32];
        int beg = rowptr[v], end = rowptr[v + 1];
        int e = beg;
        for (; e + 1 < end; e += 2) {
            int s0 = csr[e], s1 = csr[e + 1];
            const float4* r0 = (const float4*)(tp + (size_t)s0 * HDIM);
            const float4* r1 = (const float4*)(tp + (size_t)s1 * HDIM);
            float4 v00 = r0[lane], v01 = r0[lane + 32];
            float4 v10 = r1[lane], v11 = r1[lane + 32];
            a0.x += v00.x + v10.x; a0.y += v00.y + v10.y;
            a0.z += v00.z + v10.z; a0.w += v00.w + v10.w;
            a1.x += v01.x + v11.x; a1.y += v01.y + v11.y;
            a1.z += v01.z + v11.z; a1.w += v01.w + v11.w;
        }
        if (e < end) {
            int s0 = csr[e];
            const float4* r0 = (const float4*)(tp + (size_t)s0 * HDIM);
            float4 v00 = r0[lane], v01 = r0[lane + 32];
            a0.x += v00.x; a0.y += v00.y; a0.z += v00.z; a0.w += v00.w;
            a1.x += v01.x; a1.y += v01.y; a1.z += v01.z; a1.w += v01.w;
        }
        float dv = dinv[v];
        a0.x *= dv; a0.y *= dv; a0.z *= dv; a0.w *= dv;
        a1.x *= dv; a1.y *= dv; a1.z *= dv; a1.w *= dv;
        float4* hrow = (float4*)(h + (size_t)v * HDIM);
        hrow[lane]      = a0;
        hrow[lane + 32] = a1;
        ssum[0] += a0.x; ssum[1] += a0.y; ssum[2] += a0.z; ssum[3] += a0.w;
        ssum[4] += a1.x; ssum[5] += a1.y; ssum[6] += a1.z; ssum[7] += a1.w;
        ssq[0] += a0.x * a0.x; ssq[1] += a0.y * a0.y;
        ssq[2] += a0.z * a0.z; ssq[3] += a0.w * a0.w;
        ssq[4] += a1.x * a1.x; ssq[5] += a1.y * a1.y;
        ssq[6] += a1.z * a1.z; ssq[7] += a1.w * a1.w;
    }
    __syncthreads();
#pragma unroll
    for (int k = 0; k < 4; k++) {
        atomicAdd(&s_sum[lane * 4 + k], ssum[k]);
        atomicAdd(&s_sum[128 + lane * 4 + k], ssum[4 + k]);
        atomicAdd(&s_sq[lane * 4 + k], ssq[k]);
        atomicAdd(&s_sq[128 + lane * 4 + k], ssq[4 + k]);
    }
    __syncthreads();
    atomicAdd(&gsum[tid], s_sum[tid]);
    atomicAdd(&gsq[tid], s_sq[tid]);
}

// ---------------- output FC + fused combine + log-softmax -------------------
#define BM 128
#define BN 128
#define BK 16
__global__ __launch_bounds__(256, 2)
void out_gemm_kernel(const float* __restrict__ hist,
                     const float* __restrict__ sums, const float* __restrict__ sqs,
                     const float* __restrict__ gamma, const float* __restrict__ beta,
                     const float* __restrict__ w,
                     const float* __restrict__ B,
                     const float* __restrict__ bias, float* __restrict__ out,
                     int M) {
    const int Nc = C_OUT;
    const int K = HDIM;
    const size_t NH = (size_t)N_NODES * HDIM;
    __shared__ float As[2][BK][BM + 4];
    __shared__ float Bs[2][BK][BN];
    extern __shared__ float tbl[];
    float* tS  = tbl;          // [8][256]
    float* tSh = tbl + 2048;   // [8][256]
    float* tw  = tbl + 4096;   // [8]

    const int tid  = threadIdx.x;
    const int tRow = tid >> 4;
    const int tCol = tid & 15;
    const int brow = blockIdx.y * BM;
    const int am0 = tid >> 2;
    const int am1 = (tid + 256) >> 2;
    const int ak  = (tid & 3) * 4;
    const int arow0 = min(brow + am0, M - 1);
    const int arow1 = min(brow + am1, M - 1);
    const int bk0 = tid >> 5;
    const int bk1 = bk0 + 8;
    const int bnx = (tid & 31) * 4;
    const bool bok = (bnx + 3) < Nc;
    const int bcl  = bok ? bnx : 0;

    if (tid < 256) {
#pragma unroll
        for (int l = 0; l < L_LAYERS; l++) {
            float mu  = sums[l * HDIM + tid] * (1.0f / N_NODES);
            float var = sqs[l * HDIM + tid] * (1.0f / N_NODES) - mu * mu;
            float s = gamma[l * HDIM + tid] * rsqrtf(var + BN_EPS);
            tS[l * 256 + tid] = s;
            tSh[l * 256 + tid] = beta[l * HDIM + tid] - mu * s;
        }
    }
    if (tid < L_LAYERS) tw[tid] = w[tid];
    __syncthreads();

    auto combineA = [&](int row, int kc) -> float4 {
        float4 a = make_float4(0.f, 0.f, 0.f, 0.f);
#pragma unroll
        for (int l = 0; l < L_LAYERS; l++) {
            float4 v  = *(const float4*)(hist + (size_t)l * NH + (size_t)row * HDIM + kc);
            float4 s  = *(const float4*)(tS + l * 256 + kc);
            float4 sh = *(const float4*)(tSh + l * 256 + kc);
            float wl = tw[l];
            a.x = fmaf(wl, fmaxf(fmaf(v.x, s.x, sh.x), 0.f), a.x);
            a.y = fmaf(wl, fmaxf(fmaf(v.y, s.y, sh.y), 0.f), a.y);
            a.z = fmaf(wl, fmaxf(fmaf(v.z, s.z, sh.z), 0.f), a.z);
            a.w = fmaf(wl, fmaxf(fmaf(v.w, s.w, sh.w), 0.f), a.w);
        }
        return a;
    };

    unsigned long long acc[8][4];
#pragma unroll
    for (int i = 0; i < 8; i++)
#pragma unroll
        for (int j = 0; j < 4; j++) acc[i][j] = 0ull;

    float4 aR0, aR1, bR0, bR1;
    const float4 z4 = make_float4(0.f, 0.f, 0.f, 0.f);
    aR0 = combineA(arow0, ak);
    aR1 = combineA(arow1, ak);
    bR0 = bok ? *(const float4*)(B + (size_t)bk0 * Nc + bcl) : z4;
    bR1 = bok ? *(const float4*)(B + (size_t)bk1 * Nc + bcl) : z4;
    As[0][ak + 0][am0] = aR0.x; As[0][ak + 1][am0] = aR0.y;
    As[0][ak + 2][am0] = aR0.z; As[0][ak + 3][am0] = aR0.w;
    As[0][ak + 0][am1] = aR1.x; As[0][ak + 1][am1] = aR1.y;
    As[0][ak + 2][am1] = aR1.z; As[0][ak + 3][am1] = aR1.w;
    *(float4*)&Bs[0][bk0][bnx] = bR0;
    *(float4*)&Bs[0][bk1][bnx] = bR1;
    __syncthreads();

    const int nt = K / BK;
    for (int kt = 0; kt < nt; kt++) {
        const int buf = kt & 1;
        const int nxt = kt + 1;
        if (nxt < nt) {
            const int k0 = nxt * BK;
            aR0 = combineA(arow0, k0 + ak);
            aR1 = combineA(arow1, k0 + ak);
            bR0 = bok ? *(const float4*)(B + (size_t)(k0 + bk0) * Nc + bcl) : z4;
            bR1 = bok ? *(const float4*)(B + (size_t)(k0 + bk1) * Nc + bcl) : z4;
        }
#pragma unroll
        for (int k = 0; k < BK; k++) {
            float4 a0 = *(const float4*)&As[buf][k][tRow * 4];
            float4 a1 = *(const float4*)&As[buf][k][64 + tRow * 4];
            float4 b0 = *(const float4*)&Bs[buf][k][tCol * 4];
            float4 b1 = *(const float4*)&Bs[buf][k][64 + tCol * 4];
            unsigned long long bb[4] = {pk2(b0.x, b0.y), pk2(b0.z, b0.w),
                                        pk2(b1.x, b1.y), pk2(b1.z, b1.w)};
            float av[8] = {a0.x, a0.y, a0.z, a0.w, a1.x, a1.y, a1.z, a1.w};
#pragma unroll
            for (int i = 0; i < 8; i++) {
                unsigned long long ap = pk2(av[i], av[i]);
#pragma unroll
                for (int j = 0; j < 4; j++) ffma2(acc[i][j], ap, bb[j]);
            }
        }
        if (nxt < nt) {
            const int nb = nxt & 1;
            As[nb][ak + 0][am0] = aR0.x; As[nb][ak + 1][am0] = aR0.y;
            As[nb][ak + 2][am0] = aR0.z; As[nb][ak + 3][am0] = aR0.w;
            As[nb][ak + 0][am1] = aR1.x; As[nb][ak + 1][am1] = aR1.y;
            As[nb][ak + 2][am1] = aR1.z; As[nb][ak + 3][am1] = aR1.w;
            *(float4*)&Bs[nb][bk0][bnx] = bR0;
            *(float4*)&Bs[nb][bk1][bnx] = bR1;
        }
        __syncthreads();
    }

    // fused log-softmax epilogue
#pragma unroll
    for (int ih = 0; ih < 2; ih++) {
#pragma unroll
        for (int i = 0; i < 4; i++) {
            int r = brow + ih * 64 + tRow * 4 + i;
            float vals[8];
#pragma unroll
            for (int jh = 0; jh < 2; jh++) {
                float e0, e1, e2, e3;
                upk2(e0, e1, acc[ih * 4 + i][jh * 2 + 0]);
                upk2(e2, e3, acc[ih * 4 + i][jh * 2 + 1]);
                int c = jh * 64 + tCol * 4;
                vals[jh * 4 + 0] = (c + 0 < Nc) ? e0 + bias[c + 0] : -1e30f;
                vals[jh * 4 + 1] = (c + 1 < Nc) ? e1 + bias[c + 1] : -1e30f;
                vals[jh * 4 + 2] = (c + 2 < Nc) ? e2 + bias[c + 2] : -1e30f;
                vals[jh * 4 + 3] = (c + 3 < Nc) ? e3 + bias[c + 3] : -1e30f;
            }
            float m = vals[0];
#pragma unroll
            for (int j = 1; j < 8; j++) m = fmaxf(m, vals[j]);
#pragma unroll
            for (int off = 8; off >= 1; off >>= 1)
                m = fmaxf(m, __shfl_xor_sync(0xffffffffu, m, off));
            float s = 0.f;
#pragma unroll
            for (int j = 0; j < 8; j++) s += expf(vals[j] - m);
#pragma unroll
            for (int off = 8; off >= 1; off >>= 1)
                s += __shfl_xor_sync(0xffffffffu, s, off);
            float lse = m + logf(s);
            if (r < M) {
#pragma unroll
                for (int jh = 0; jh < 2; jh++) {
                    int c = jh * 64 + tCol * 4;
#pragma unroll
                    for (int j = 0; j < 4; j++)
                        if (c + j < Nc)
                            out[(size_t)r * Nc + c + j] = vals[jh * 4 + j] - lse;
                }
            }
        }
    }
}

// ---------------- host launcher ---------------------------------------------
extern "C" void kernel_launch(void* const* d_in, const int* in_sizes, int n_in,
                              void* d_out, int out_size) {
    const float* x       = (const float*)d_in[0];
    const int*   e1      = (const int*)  d_in[1];
    const int*   e2      = (const int*)  d_in[2];
    const float* in_W    = (const float*)d_in[3];
    const float* in_b    = (const float*)d_in[4];
    const float* convW   = (const float*)d_in[5];
    const float* convB   = (const float*)d_in[6];
    const float* bng     = (const float*)d_in[7];
    const float* bnb     = (const float*)d_in[8];
    const float* out_W   = (const float*)d_in[9];
    const float* out_b   = (const float*)d_in[10];
    const float* layer_w = (const float*)d_in[11];
    float* out = (float*)d_out;

    float *p_h0, *p_t, *p_hist, *p_dinv1, *p_dinv2, *p_sums, *p_sqs, *p_w;
    __nv_bfloat16 *p_wth, *p_wtl, *p_inwh, *p_inwl;
    int *p_cnt1, *p_cnt2, *p_rp1, *p_rp2, *p_cur1, *p_cur2, *p_csr1, *p_csr2;
    cudaGetSymbolAddress((void**)&p_h0, g_h0);
    cudaGetSymbolAddress((void**)&p_t, g_t);
    cudaGetSymbolAddress((void**)&p_hist, g_hist);
    cudaGetSymbolAddress((void**)&p_wth, g_wth);
    cudaGetSymbolAddress((void**)&p_wtl, g_wtl);
    cudaGetSymbolAddress((void**)&p_inwh, g_inwh);
    cudaGetSymbolAddress((void**)&p_inwl, g_inwl);
    cudaGetSymbolAddress((void**)&p_dinv1, g_dinv1);
    cudaGetSymbolAddress((void**)&p_dinv2, g_dinv2);
    cudaGetSymbolAddress((void**)&p_sums, g_sums);
    cudaGetSymbolAddress((void**)&p_sqs, g_sqs);
    cudaGetSymbolAddress((void**)&p_w, g_w);
    cudaGetSymbolAddress((void**)&p_cnt1, g_cnt1);
    cudaGetSymbolAddress((void**)&p_cnt2, g_cnt2);
    cudaGetSymbolAddress((void**)&p_rp1, g_rp1);
    cudaGetSymbolAddress((void**)&p_rp2, g_rp2);
    cudaGetSymbolAddress((void**)&p_cur1, g_cur1);
    cudaGetSymbolAddress((void**)&p_cur2, g_cur2);
    cudaGetSymbolAddress((void**)&p_csr1, g_csr1);
    cudaGetSymbolAddress((void**)&p_csr2, g_csr2);

    const int outSmem = (2048 + 2048 + 8) * sizeof(float);   // 16416 B dynamic
    cudaFuncSetAttribute(mma_gemm_kernel,
                         cudaFuncAttributeMaxDynamicSharedMemorySize, MG_SMEM);
    cudaFuncSetAttribute(out_gemm_kernel,
                         cudaFuncAttributeMaxDynamicSharedMemorySize, outSmem);

    const int nThr = 256;
    const int nbE  = (E_EDGES + nThr - 1) / nThr;
    const int nbW  = (L_LAYERS * HDIM * HDIM + nThr - 1) / nThr;
    const dim3 outGrid(1, (N_NODES + BM - 1) / BM);
    const dim3 mmaGrid(2, (N_NODES + 127) / 128);
    const int aggBlocks = 1480;
    const size_t NH = (size_t)N_NODES * HDIM;

    prep_kernel<<<nbW, nThr>>>(convW, in_W, layer_w, p_wth, p_wtl,
                               p_inwh, p_inwl, p_sums, p_sqs, p_w,
                               p_cnt1, p_cnt2);

    // input FC on the tensor path: h0 = x @ in_W + in_b  (K=128, no BN/dinv)
    mma_gemm_kernel<<<mmaGrid, nThr, MG_SMEM>>>(
        x, F_INPUT, nullptr, nullptr, nullptr, nullptr, 0,
        p_inwh, p_inwl, in_b, nullptr, p_h0, N_NODES);

    hist2_kernel<<<nbE, nThr>>>(e1 + E_EDGES, e2 + E_EDGES, p_cnt1, p_cnt2);
    scan2_kernel<<<2, 1024>>>(p_cnt1, p_cnt2, p_rp1, p_rp2,
                              p_dinv1, p_dinv2, p_cur1, p_cur2);
    fill2_kernel<<<nbE, nThr>>>(e1, e2, p_cur1, p_cur2, p_csr1, p_csr2);

    for (int l = 0; l < L_LAYERS; l++) {
        const int*   rp   = (l < L_LAYERS / 2) ? p_rp1 : p_rp2;
        const int*   csr  = (l < L_LAYERS / 2) ? p_csr1 : p_csr2;
        const float* dinv = (l < L_LAYERS / 2) ? p_dinv1 : p_dinv2;
        const float* Hin  = (l == 0) ? p_h0 : p_hist + (size_t)(l - 1) * NH;
        const float* bs   = (l == 0) ? p_sums : p_sums + (l - 1) * HDIM;
        const float* bq   = (l == 0) ? p_sqs  : p_sqs + (l - 1) * HDIM;
        const float* bg   = (l == 0) ? bng : bng + (l - 1) * HDIM;
        const float* bb   = (l == 0) ? bnb : bnb + (l - 1) * HDIM;

        mma_gemm_kernel<<<mmaGrid, nThr, MG_SMEM>>>(
            Hin, HDIM, bs, bq, bg, bb, (l > 0) ? 1 : 0,
            p_wth + (size_t)l * HDIM * HDIM, p_wtl + (size_t)l * HDIM * HDIM,
            convB + l * HDIM, dinv, p_t, N_NODES);
        agg_kernel<<<aggBlocks, nThr>>>(rp, csr, dinv, p_t,
                                        p_hist + (size_t)l * NH,
                                        p_sums + l * HDIM, p_sqs + l * HDIM);
    }

    out_gemm_kernel<<<outGrid, nThr, outSmem>>>(
        p_hist, p_sums, p_sqs, bng, bnb, p_w, out_W, out_b, out, N_NODES);
}

// round 15
// speedup vs baseline: 1.0117x; 1.0117x over previous
#include <cuda_runtime.h>
#include <cuda_bf16.h>
#include <math.h>
#include <stdint.h>

#define N_NODES 50000
#define E_EDGES 800000
#define F_INPUT 128
#define HDIM    256
#define C_OUT   112
#define L_LAYERS 8
#define BN_EPS  1e-5f
#define NSEG    13
#define SEGSZ   4096

// ---------------- scratch (device globals; no allocations anywhere) --------
__device__ float g_h0[N_NODES * HDIM];                       // input FC output
__device__ float g_t[N_NODES * HDIM];                        // t' per layer
__device__ float g_hist[L_LAYERS * N_NODES * HDIM];          // raw agg out per layer
__device__ __nv_bfloat16 g_wth[L_LAYERS * HDIM * HDIM];      // convW^T hi [l][n][k]
__device__ __nv_bfloat16 g_wtl[L_LAYERS * HDIM * HDIM];      // convW^T lo
__device__ __nv_bfloat16 g_inwh[HDIM * F_INPUT];             // in_W^T hi [n][k]
__device__ __nv_bfloat16 g_inwl[HDIM * F_INPUT];             // in_W^T lo
__device__ float g_dinv1[N_NODES];
__device__ float g_dinv2[N_NODES];
__device__ float g_sums[L_LAYERS * HDIM];
__device__ float g_sqs[L_LAYERS * HDIM];
__device__ float g_w[L_LAYERS];
__device__ int g_cnt1[N_NODES];
__device__ int g_cnt2[N_NODES];
__device__ int g_part[2 * NSEG];
__device__ int g_rp1[N_NODES + 1];
__device__ int g_rp2[N_NODES + 1];
__device__ int g_cur1[N_NODES];
__device__ int g_cur2[N_NODES];
__device__ int g_csr1[E_EDGES];
__device__ int g_csr2[E_EDGES];

// ---------------- helpers ---------------------------------------------------
__device__ __forceinline__ uint32_t smem_u32(const void* p) {
    uint32_t a;
    asm("{ .reg .u64 t; cvta.to.shared.u64 t, %1; cvt.u32.u64 %0, t; }"
        : "=r"(a) : "l"(p));
    return a;
}
__device__ __forceinline__ unsigned long long pk2(float lo, float hi) {
    unsigned long long r;
    asm("mov.b64 %0, {%1, %2};" : "=l"(r) : "f"(lo), "f"(hi));
    return r;
}
__device__ __forceinline__ void upk2(float& lo, float& hi, unsigned long long v) {
    asm("mov.b64 {%0, %1}, %2;" : "=f"(lo), "=f"(hi) : "l"(v));
}
__device__ __forceinline__ void ffma2(unsigned long long& d,
                                      unsigned long long a, unsigned long long b) {
    asm("fma.rn.f32x2 %0, %1, %2, %0;" : "+l"(d) : "l"(a), "l"(b));
}
__device__ __forceinline__ void ldm_x4(uint32_t& r0, uint32_t& r1,
                                       uint32_t& r2, uint32_t& r3, uint32_t addr) {
    asm volatile("ldmatrix.sync.aligned.m8n8.x4.shared.b16 {%0,%1,%2,%3}, [%4];"
                 : "=r"(r0), "=r"(r1), "=r"(r2), "=r"(r3) : "r"(addr));
}
__device__ __forceinline__ void mma_bf16(float* d, const uint32_t* a,
                                         uint32_t b0, uint32_t b1) {
    asm volatile(
        "mma.sync.aligned.m16n8k16.row.col.f32.bf16.bf16.f32 "
        "{%0,%1,%2,%3}, {%4,%5,%6,%7}, {%8,%9}, {%0,%1,%2,%3};"
        : "+f"(d[0]), "+f"(d[1]), "+f"(d[2]), "+f"(d[3])
        : "r"(a[0]), "r"(a[1]), "r"(a[2]), "r"(a[3]), "r"(b0), "r"(b1));
}
__device__ __forceinline__ void cpa16(uint32_t dst, const void* src) {
    asm volatile("cp.async.cg.shared.global [%0], [%1], 16;"
                 :: "r"(dst), "l"(src));
}
__device__ __forceinline__ uint32_t bf2pack(__nv_bfloat16 a, __nv_bfloat16 b) {
    __nv_bfloat162 p = {a, b};
    return *(uint32_t*)&p;
}

// ---------------- prep: weight splits + zero stats/cnts + softmax(w) --------
__global__ void prep_kernel(const float* __restrict__ convW,
                            const float* __restrict__ in_W,
                            const float* __restrict__ lw,
                            __nv_bfloat16* wth, __nv_bfloat16* wtl,
                            __nv_bfloat16* inwh, __nv_bfloat16* inwl,
                            float* sums, float* sqs, float* w,
                            int* cnt1, int* cnt2) {
    int i = blockIdx.x * blockDim.x + threadIdx.x;
    if (i < L_LAYERS * HDIM) { sums[i] = 0.f; sqs[i] = 0.f; }
    if (i < N_NODES) { cnt1[i] = 0; cnt2[i] = 0; }
    if (i == 0) {
        float m = -1e30f;
        for (int l = 0; l < L_LAYERS; l++) m = fmaxf(m, lw[l]);
        float s = 0.f;
        for (int l = 0; l < L_LAYERS; l++) s += expf(lw[l] - m);
        for (int l = 0; l < L_LAYERS; l++) w[l] = expf(lw[l] - m) / s;
    }
    if (i < HDIM * F_INPUT) {   // in_W^T split: [n=256][k=128]
        int n = i / F_INPUT;
        int k = i % F_INPUT;
        float v = in_W[k * HDIM + n];
        __nv_bfloat16 hi = __float2bfloat16(v);
        inwh[i] = hi;
        inwl[i] = __float2bfloat16(v - __bfloat162float(hi));
    }
    if (i >= L_LAYERS * HDIM * HDIM) return;
    int l = i >> 16;
    int n = (i >> 8) & 255;
    int k = i & 255;
    float v = convW[(l << 16) + (k << 8) + n];
    __nv_bfloat16 hi = __float2bfloat16(v);
    wth[i] = hi;
    wtl[i] = __float2bfloat16(v - __bfloat162float(hi));
}

// ---------------- CSR build (both adjacencies per launch) -------------------
__global__ void hist2_kernel(const int* __restrict__ t1, const int* __restrict__ t2,
                             int* c1, int* c2) {
    int i = blockIdx.x * blockDim.x + threadIdx.x;
    if (i < E_EDGES) {
        atomicAdd(&c1[t1[i]], 1);
        atomicAdd(&c2[t2[i]], 1);
    }
}

// phase 1: per-segment totals. grid (NSEG, 2), 256 thr.
__global__ void partial2_kernel(const int* __restrict__ c1,
                                const int* __restrict__ c2, int* partials) {
    const int* cnt = blockIdx.y ? c2 : c1;
    int base = blockIdx.x * SEGSZ + threadIdx.x * 16;
    int s = 0;
#pragma unroll
    for (int i = 0; i < 16; i += 4) {
        int idx = base + i;
        if (idx + 3 < N_NODES) {
            int4 v = *(const int4*)(cnt + idx);
            s += v.x + v.y + v.z + v.w;
        } else {
#pragma unroll
            for (int j = 0; j < 4; j++)
                if (idx + j < N_NODES) s += cnt[idx + j];
        }
    }
    __shared__ int ws[8];
#pragma unroll
    for (int off = 16; off >= 1; off >>= 1)
        s += __shfl_xor_sync(0xffffffffu, s, off);
    if ((threadIdx.x & 31) == 0) ws[threadIdx.x >> 5] = s;
    __syncthreads();
    if (threadIdx.x == 0) {
        int t = 0;
#pragma unroll
        for (int w2 = 0; w2 < 8; w2++) t += ws[w2];
        partials[blockIdx.y * NSEG + blockIdx.x] = t;
    }
}

// phase 2: in-segment scan + emit rowptr/cursor/dinv. grid (NSEG, 2), 256 thr.
__global__ void scanemit2_kernel(const int* __restrict__ c1,
                                 const int* __restrict__ c2,
                                 const int* __restrict__ partials,
                                 int* r1, int* r2,
                                 float* d1, float* d2, int* cu1, int* cu2) {
    const int* cnt = blockIdx.y ? c2 : c1;
    int* rowptr    = blockIdx.y ? r2 : r1;
    float* dinv    = blockIdx.y ? d2 : d1;
    int* cur       = blockIdx.y ? cu2 : cu1;
    const int seg = blockIdx.x;
    int segbase = 0;
    for (int s2 = 0; s2 < seg; s2++) segbase += partials[blockIdx.y * NSEG + s2];

    const int tid = threadIdx.x, lane = tid & 31, wid = tid >> 5;
    const int base = seg * SEGSZ + tid * 16;
    int c[16];
    int loc = 0;
#pragma unroll
    for (int i = 0; i < 16; i += 4) {
        int idx = base + i;
        if (idx + 3 < N_NODES) {
            int4 v = *(const int4*)(cnt + idx);
            c[i] = v.x; c[i + 1] = v.y; c[i + 2] = v.z; c[i + 3] = v.w;
        } else {
#pragma unroll
            for (int j = 0; j < 4; j++)
                c[i + j] = (idx + j < N_NODES) ? cnt[idx + j] : 0;
        }
        loc += c[i] + c[i + 1] + c[i + 2] + c[i + 3];
    }
    int v = loc;
#pragma unroll
    for (int off = 1; off < 32; off <<= 1) {
        int n = __shfl_up_sync(0xffffffffu, v, off);
        if (lane >= off) v += n;
    }
    __shared__ int wsum[8];
    if (lane == 31) wsum[wid] = v;
    __syncthreads();
    int woff = 0;
    for (int w2 = 0; w2 < wid; w2++) woff += wsum[w2];
    int run = segbase + woff + v - loc;    // exclusive prefix
#pragma unroll
    for (int i = 0; i < 16; i++) {
        int idx = base + i;
        if (idx < N_NODES) {
            rowptr[idx] = run;
            cur[idx]    = run;
            dinv[idx]   = rsqrtf((float)c[i] + 1.0f);
            run += c[i];
        }
    }
    if (seg == NSEG - 1 && tid == 255) rowptr[N_NODES] = run;
}

__global__ void fill2_kernel(const int* __restrict__ e1, const int* __restrict__ e2,
                             int* cu1, int* cu2, int* cs1, int* cs2) {
    int i = blockIdx.x * blockDim.x + threadIdx.x;
    if (i < E_EDGES) {
        int p1 = atomicAdd(&cu1[e1[E_EDGES + i]], 1);
        cs1[p1] = e1[i];
        int p2 = atomicAdd(&cu2[e2[E_EDGES + i]], 1);
        cs2[p2] = e2[i];
    }
}

// ---------------- mma.sync GEMM, fused BN+ReLU+bf16-split A-staging --------
// C[M,256] = bf16split(relu?(bn?(Hin[M,K]))) @ B^T + bias, opt * dinv.
// CTA 128x128, warp 32x64, K chunk 32 (K = 128 or 256), double-buffered.
#define SROW 40
#define ABUF (128 * SROW * 2)                 // 10240 B per array per buffer
#define MG_SMEM (8 * ABUF + 2048)             // + bn param tables

__global__ __launch_bounds__(256, 2)
void mma_gemm_kernel(const float* __restrict__ Hin, int K,
                     const float* __restrict__ bsum, const float* __restrict__ bsq,
                     const float* __restrict__ gamma, const float* __restrict__ beta,
                     int do_bn,
                     const __nv_bfloat16* __restrict__ Bh,
                     const __nv_bfloat16* __restrict__ Bl,
                     const float* __restrict__ bias,
                     const float* __restrict__ dinv,
                     float* __restrict__ C, int M) {
    extern __shared__ char dsm[];
    float* sS  = (float*)(dsm + 8 * ABUF);
    float* sSh = sS + 256;
    const uint32_t sb = smem_u32(dsm);
    const int tid  = threadIdx.x;
    const int lane = tid & 31;
    const int wid  = tid >> 5;
    const int wm   = wid & 3;
    const int wn   = wid >> 2;
    const int brow = blockIdx.y * 128;
    const int bcol = blockIdx.x * 128;
    const int nch  = K >> 5;

    if (tid < 256) {
        if (do_bn) {
            float mu  = bsum[tid] * (1.0f / N_NODES);
            float var = bsq[tid] * (1.0f / N_NODES) - mu * mu;
            float s = gamma[tid] * rsqrtf(var + BN_EPS);
            sS[tid] = s;
            sSh[tid] = beta[tid] - mu * s;
        } else {
            sS[tid] = 1.f;
            sSh[tid] = 0.f;
        }
    }

    const int r0 = tid >> 2, r1 = r0 + 64, sg = tid & 3;
    const int gr0 = min(brow + r0, M - 1);
    const int gr1 = min(brow + r1, M - 1);
    const int wn0 = bcol + r0, wn1 = bcol + r1;
    const uint32_t d0 = (uint32_t)(r0 * SROW + sg * 8) * 2;
    const uint32_t d1 = (uint32_t)(r1 * SROW + sg * 8) * 2;

    auto issueB = [&](int c) {
        const int kb = c * 32 + sg * 8;
        const uint32_t bo = (uint32_t)(c & 1) * ABUF;
        cpa16(sb + 4 * ABUF + bo + d0, Bh + (size_t)wn0 * K + kb);
        cpa16(sb + 4 * ABUF + bo + d1, Bh + (size_t)wn1 * K + kb);
        cpa16(sb + 6 * ABUF + bo + d0, Bl + (size_t)wn0 * K + kb);
        cpa16(sb + 6 * ABUF + bo + d1, Bl + (size_t)wn1 * K + kb);
        asm volatile("cp.async.commit_group;");
    };

    float4 ar[4];
    auto loadA = [&](int c) {
        const int kb = c * 32 + sg * 8;
        ar[0] = *(const float4*)(Hin + (size_t)gr0 * K + kb);
        ar[1] = *(const float4*)(Hin + (size_t)gr0 * K + kb + 4);
        ar[2] = *(const float4*)(Hin + (size_t)gr1 * K + kb);
        ar[3] = *(const float4*)(Hin + (size_t)gr1 * K + kb + 4);
    };
    auto stageA = [&](int c) {
        const int kb = c * 32 + sg * 8;
        const uint32_t bo = (uint32_t)(c & 1) * ABUF;
        float s[8], sh[8];
#pragma unroll
        for (int j = 0; j < 8; j++) { s[j] = sS[kb + j]; sh[j] = sSh[kb + j]; }
        const float* av = (const float*)ar;
        uint32_t hiw[4], low[4];
#pragma unroll
        for (int rr = 0; rr < 2; rr++) {
            __nv_bfloat16 hb[8], lb[8];
#pragma unroll
            for (int j = 0; j < 8; j++) {
                float v = fmaf(av[rr * 8 + j], s[j], sh[j]);
                if (do_bn) v = fmaxf(v, 0.f);
                hb[j] = __float2bfloat16(v);
                lb[j] = __float2bfloat16(v - __bfloat162float(hb[j]));
            }
#pragma unroll
            for (int j = 0; j < 4; j++) {
                hiw[j] = bf2pack(hb[2 * j], hb[2 * j + 1]);
                low[j] = bf2pack(lb[2 * j], lb[2 * j + 1]);
            }
            const uint32_t dd = rr ? d1 : d0;
            *(uint4*)(dsm + bo + dd)            = *(uint4*)hiw;
            *(uint4*)(dsm + 2 * ABUF + bo + dd) = *(uint4*)low;
        }
    };

    // ldmatrix lane offsets
    const int li = lane & 7;
    const int lb_ = (lane >> 3) & 1;
    const int lc = (lane >> 4) & 1;
    uint32_t aoff[2], boff[4];
#pragma unroll
    for (int mf = 0; mf < 2; mf++)
        aoff[mf] = (uint32_t)((wm * 32 + mf * 16 + lb_ * 8 + li) * SROW + lc * 8) * 2;
#pragma unroll
    for (int nf = 0; nf < 4; nf++)
        boff[nf] = (uint32_t)((wn * 64 + nf * 16 + lc * 8 + li) * SROW + lb_ * 8) * 2;

    float acc[2][8][4];
#pragma unroll
    for (int i = 0; i < 2; i++)
#pragma unroll
        for (int j = 0; j < 8; j++)
#pragma unroll
            for (int k = 0; k < 4; k++) acc[i][j][k] = 0.f;

    issueB(0);
    loadA(0);
    __syncthreads();        // sS/sSh ready
    stageA(0);

    for (int c = 0; c < nch; c++) {
        asm volatile("cp.async.wait_group 0;" ::: "memory");
        __syncthreads();    // A(c)+B(c) visible; all MMA(c-1) reads done
        if (c + 1 < nch) { issueB(c + 1); loadA(c + 1); }

        const uint32_t bo  = (uint32_t)(c & 1) * ABUF;
        const uint32_t bAh = sb + bo;
        const uint32_t bAl = sb + 2 * ABUF + bo;
        const uint32_t bBh = sb + 4 * ABUF + bo;
        const uint32_t bBl = sb + 6 * ABUF + bo;
#pragma unroll
        for (int ks = 0; ks < 2; ks++) {
            const uint32_t kadd = ks * 32;
            uint32_t A0h[4], A1h[4], A0l[4], A1l[4];
            ldm_x4(A0h[0], A0h[1], A0h[2], A0h[3], bAh + aoff[0] + kadd);
            ldm_x4(A1h[0], A1h[1], A1h[2], A1h[3], bAh + aoff[1] + kadd);
            ldm_x4(A0l[0], A0l[1], A0l[2], A0l[3], bAl + aoff[0] + kadd);
            ldm_x4(A1l[0], A1l[1], A1l[2], A1l[3], bAl + aoff[1] + kadd);
#pragma unroll
            for (int nf = 0; nf < 4; nf++) {
                uint32_t bh[4], bl[4];
                ldm_x4(bh[0], bh[1], bh[2], bh[3], bBh + boff[nf] + kadd);
                ldm_x4(bl[0], bl[1], bl[2], bl[3], bBl + boff[nf] + kadd);
                mma_bf16(acc[0][nf * 2 + 0], A0h, bh[0], bh[1]);
                mma_bf16(acc[0][nf * 2 + 0], A0h, bl[0], bl[1]);
                mma_bf16(acc[0][nf * 2 + 0], A0l, bh[0], bh[1]);
                mma_bf16(acc[0][nf * 2 + 1], A0h, bh[2], bh[3]);
                mma_bf16(acc[0][nf * 2 + 1], A0h, bl[2], bl[3]);
                mma_bf16(acc[0][nf * 2 + 1], A0l, bh[2], bh[3]);
                mma_bf16(acc[1][nf * 2 + 0], A1h, bh[0], bh[1]);
                mma_bf16(acc[1][nf * 2 + 0], A1h, bl[0], bl[1]);
                mma_bf16(acc[1][nf * 2 + 0], A1l, bh[0], bh[1]);
                mma_bf16(acc[1][nf * 2 + 1], A1h, bh[2], bh[3]);
                mma_bf16(acc[1][nf * 2 + 1], A1h, bl[2], bl[3]);
                mma_bf16(acc[1][nf * 2 + 1], A1l, bh[2], bh[3]);
            }
        }
        if (c + 1 < nch) stageA(c + 1);
    }

    // epilogue: C[r, c] = (acc + bias[c]) * (dinv ? dinv[r] : 1)
    const int qr = lane >> 2;
    const int qc = (lane & 3) * 2;
#pragma unroll
    for (int mf = 0; mf < 2; mf++) {
        int rr0 = brow + wm * 32 + mf * 16 + qr;
        int rr1 = rr0 + 8;
        float dv0 = (rr0 < M) ? (dinv ? dinv[rr0] : 1.0f) : 0.f;
        float dv1 = (rr1 < M) ? (dinv ? dinv[rr1] : 1.0f) : 0.f;
#pragma unroll
        for (int nf = 0; nf < 8; nf++) {
            int cc = bcol + wn * 64 + nf * 8 + qc;
            float b0 = bias[cc], b1 = bias[cc + 1];
            if (rr0 < M)
                *(float2*)(C + (size_t)rr0 * HDIM + cc) =
                    make_float2((acc[mf][nf][0] + b0) * dv0,
                                (acc[mf][nf][1] + b1) * dv0);
            if (rr1 < M)
                *(float2*)(C + (size_t)rr1 * HDIM + cc) =
                    make_float2((acc[mf][nf][2] + b0) * dv1,
                                (acc[mf][nf][3] + b1) * dv1);
        }
    }
}

// ---------------- CSR aggregation + fused BN stats ---------------------------
__global__ __launch_bounds__(256)
void agg_kernel(const int* __restrict__ rowptr, const int* __restrict__ csr,
                const float* __restrict__ dinv, const float* __restrict__ tp,
                float* __restrict__ h, float* gsum, float* gsq) {
    __shared__ float s_sum[HDIM];
    __shared__ float s_sq[HDIM];
    int tid  = threadIdx.x;
    int lane = tid & 31;
    int warp = tid >> 5;
    int gw   = blockIdx.x * 8 + warp;
    int nw   = gridDim.x * 8;

    s_sum[tid] = 0.f;
    s_sq[tid]  = 0.f;

    float ssum[8], ssq[8];
#pragma unroll
    for (int i = 0; i < 8; i++) { ssum[i] = 0.f; ssq[i] = 0.f; }

    for (int v = gw; v < N_NODES; v += nw) {
        const float4* self = (const float4*)(tp + (size_t)v * HDIM);
        float4 a0 = self[lane];
        float4 a1 = self[lane + 32];
        int beg = rowptr[v], end = rowptr[v + 1];
        int e = beg;
        for (; e + 1 < end; e += 2) {
            int s0 = csr[e], s1 = csr[e + 1];
            const float4* r0 = (const float4*)(tp + (size_t)s0 * HDIM);
            const float4* r1 = (const float4*)(tp + (size_t)s1 * HDIM);
            float4 v00 = r0[lane], v01 = r0[lane + 32];
            float4 v10 = r1[lane], v11 = r1[lane + 32];
            a0.x += v00.x + v10.x; a0.y += v00.y + v10.y;
            a0.z += v00.z + v10.z; a0.w += v00.w + v10.w;
            a1.x += v01.x + v11.x; a1.y += v01.y + v11.y;
            a1.z += v01.z + v11.z; a1.w += v01.w + v11.w;
        }
        if (e < end) {
            int s0 = csr[e];
            const float4* r0 = (const float4*)(tp + (size_t)s0 * HDIM);
            float4 v00 = r0[lane], v01 = r0[lane + 32];
            a0.x += v00.x; a0.y += v00.y; a0.z += v00.z; a0.w += v00.w;
            a1.x += v01.x; a1.y += v01.y; a1.z += v01.z; a1.w += v01.w;
        }
        float dv = dinv[v];
        a0.x *= dv; a0.y *= dv; a0.z *= dv; a0.w *= dv;
        a1.x *= dv; a1.y *= dv; a1.z *= dv; a1.w *= dv;
        float4* hrow = (float4*)(h + (size_t)v * HDIM);
        hrow[lane]      = a0;
        hrow[lane + 32] = a1;
        ssum[0] += a0.x; ssum[1] += a0.y; ssum[2] += a0.z; ssum[3] += a0.w;
        ssum[4] += a1.x; ssum[5] += a1.y; ssum[6] += a1.z; ssum[7] += a1.w;
        ssq[0] += a0.x * a0.x; ssq[1] += a0.y * a0.y;
        ssq[2] += a0.z * a0.z; ssq[3] += a0.w * a0.w;
        ssq[4] += a1.x * a1.x; ssq[5] += a1.y * a1.y;
        ssq[6] += a1.z * a1.z; ssq[7] += a1.w * a1.w;
    }
    __syncthreads();
#pragma unroll
    for (int k = 0; k < 4; k++) {
        atomicAdd(&s_sum[lane * 4 + k], ssum[k]);
        atomicAdd(&s_sum[128 + lane * 4 + k], ssum[4 + k]);
        atomicAdd(&s_sq[lane * 4 + k], ssq[k]);
        atomicAdd(&s_sq[128 + lane * 4 + k], ssq[4 + k]);
    }
    __syncthreads();
    atomicAdd(&gsum[tid], s_sum[tid]);
    atomicAdd(&gsq[tid], s_sq[tid]);
}

// ---------------- output FC + fused combine + log-softmax -------------------
#define BM 128
#define BN 128
#define BK 16
__global__ __launch_bounds__(256, 2)
void out_gemm_kernel(const float* __restrict__ hist,
                     const float* __restrict__ sums, const float* __restrict__ sqs,
                     const float* __restrict__ gamma, const float* __restrict__ beta,
                     const float* __restrict__ w,
                     const float* __restrict__ B,
                     const float* __restrict__ bias, float* __restrict__ out,
                     int M) {
    const int Nc = C_OUT;
    const int K = HDIM;
    const size_t NH = (size_t)N_NODES * HDIM;
    __shared__ float As[2][BK][BM + 4];
    __shared__ float Bs[2][BK][BN];
    extern __shared__ float tbl[];
    float* tS  = tbl;          // [8][256]
    float* tSh = tbl + 2048;   // [8][256]
    float* tw  = tbl + 4096;   // [8]

    const int tid  = threadIdx.x;
    const int tRow = tid >> 4;
    const int tCol = tid & 15;
    const int brow = blockIdx.y * BM;
    const int am0 = tid >> 2;
    const int am1 = (tid + 256) >> 2;
    const int ak  = (tid & 3) * 4;
    const int arow0 = min(brow + am0, M - 1);
    const int arow1 = min(brow + am1, M - 1);
    const int bk0 = tid >> 5;
    const int bk1 = bk0 + 8;
    const int bnx = (tid & 31) * 4;
    const bool bok = (bnx + 3) < Nc;
    const int bcl  = bok ? bnx : 0;

    if (tid < 256) {
#pragma unroll
        for (int l = 0; l < L_LAYERS; l++) {
            float mu  = sums[l * HDIM + tid] * (1.0f / N_NODES);
            float var = sqs[l * HDIM + tid] * (1.0f / N_NODES) - mu * mu;
            float s = gamma[l * HDIM + tid] * rsqrtf(var + BN_EPS);
            tS[l * 256 + tid] = s;
            tSh[l * 256 + tid] = beta[l * HDIM + tid] - mu * s;
        }
    }
    if (tid < L_LAYERS) tw[tid] = w[tid];
    __syncthreads();

    auto combineA = [&](int row, int kc) -> float4 {
        float4 a = make_float4(0.f, 0.f, 0.f, 0.f);
#pragma unroll
        for (int l = 0; l < L_LAYERS; l++) {
            float4 v  = *(const float4*)(hist + (size_t)l * NH + (size_t)row * HDIM + kc);
            float4 s  = *(const float4*)(tS + l * 256 + kc);
            float4 sh = *(const float4*)(tSh + l * 256 + kc);
            float wl = tw[l];
            a.x = fmaf(wl, fmaxf(fmaf(v.x, s.x, sh.x), 0.f), a.x);
            a.y = fmaf(wl, fmaxf(fmaf(v.y, s.y, sh.y), 0.f), a.y);
            a.z = fmaf(wl, fmaxf(fmaf(v.z, s.z, sh.z), 0.f), a.z);
            a.w = fmaf(wl, fmaxf(fmaf(v.w, s.w, sh.w), 0.f), a.w);
        }
        return a;
    };

    unsigned long long acc[8][4];
#pragma unroll
    for (int i = 0; i < 8; i++)
#pragma unroll
        for (int j = 0; j < 4; j++) acc[i][j] = 0ull;

    float4 aR0, aR1, bR0, bR1;
    const float4 z4 = make_float4(0.f, 0.f, 0.f, 0.f);
    aR0 = combineA(arow0, ak);
    aR1 = combineA(arow1, ak);
    bR0 = bok ? *(const float4*)(B + (size_t)bk0 * Nc + bcl) : z4;
    bR1 = bok ? *(const float4*)(B + (size_t)bk1 * Nc + bcl) : z4;
    As[0][ak + 0][am0] = aR0.x; As[0][ak + 1][am0] = aR0.y;
    As[0][ak + 2][am0] = aR0.z; As[0][ak + 3][am0] = aR0.w;
    As[0][ak + 0][am1] = aR1.x; As[0][ak + 1][am1] = aR1.y;
    As[0][ak + 2][am1] = aR1.z; As[0][ak + 3][am1] = aR1.w;
    *(float4*)&Bs[0][bk0][bnx] = bR0;
    *(float4*)&Bs[0][bk1][bnx] = bR1;
    __syncthreads();

    const int nt = K / BK;
    for (int kt = 0; kt < nt; kt++) {
        const int buf = kt & 1;
        const int nxt = kt + 1;
        if (nxt < nt) {
            const int k0 = nxt * BK;
            aR0 = combineA(arow0, k0 + ak);
            aR1 = combineA(arow1, k0 + ak);
            bR0 = bok ? *(const float4*)(B + (size_t)(k0 + bk0) * Nc + bcl) : z4;
            bR1 = bok ? *(const float4*)(B + (size_t)(k0 + bk1) * Nc + bcl) : z4;
        }
#pragma unroll
        for (int k = 0; k < BK; k++) {
            float4 a0 = *(const float4*)&As[buf][k][tRow * 4];
            float4 a1 = *(const float4*)&As[buf][k][64 + tRow * 4];
            float4 b0 = *(const float4*)&Bs[buf][k][tCol * 4];
            float4 b1 = *(const float4*)&Bs[buf][k][64 + tCol * 4];
            unsigned long long bb[4] = {pk2(b0.x, b0.y), pk2(b0.z, b0.w),
                                        pk2(b1.x, b1.y), pk2(b1.z, b1.w)};
            float av[8] = {a0.x, a0.y, a0.z, a0.w, a1.x, a1.y, a1.z, a1.w};
#pragma unroll
            for (int i = 0; i < 8; i++) {
                unsigned long long ap = pk2(av[i], av[i]);
#pragma unroll
                for (int j = 0; j < 4; j++) ffma2(acc[i][j], ap, bb[j]);
            }
        }
        if (nxt < nt) {
            const int nb = nxt & 1;
            As[nb][ak + 0][am0] = aR0.x; As[nb][ak + 1][am0] = aR0.y;
            As[nb][ak + 2][am0] = aR0.z; As[nb][ak + 3][am0] = aR0.w;
            As[nb][ak + 0][am1] = aR1.x; As[nb][ak + 1][am1] = aR1.y;
            As[nb][ak + 2][am1] = aR1.z; As[nb][ak + 3][am1] = aR1.w;
            *(float4*)&Bs[nb][bk0][bnx] = bR0;
            *(float4*)&Bs[nb][bk1][bnx] = bR1;
        }
        __syncthreads();
    }

    // fused log-softmax epilogue
#pragma unroll
    for (int ih = 0; ih < 2; ih++) {
#pragma unroll
        for (int i = 0; i < 4; i++) {
            int r = brow + ih * 64 + tRow * 4 + i;
            float vals[8];
#pragma unroll
            for (int jh = 0; jh < 2; jh++) {
                float e0, e1, e2, e3;
                upk2(e0, e1, acc[ih * 4 + i][jh * 2 + 0]);
                upk2(e2, e3, acc[ih * 4 + i][jh * 2 + 1]);
                int c = jh * 64 + tCol * 4;
                vals[jh * 4 + 0] = (c + 0 < Nc) ? e0 + bias[c + 0] : -1e30f;
                vals[jh * 4 + 1] = (c + 1 < Nc) ? e1 + bias[c + 1] : -1e30f;
                vals[jh * 4 + 2] = (c + 2 < Nc) ? e2 + bias[c + 2] : -1e30f;
                vals[jh * 4 + 3] = (c + 3 < Nc) ? e3 + bias[c + 3] : -1e30f;
            }
            float m = vals[0];
#pragma unroll
            for (int j = 1; j < 8; j++) m = fmaxf(m, vals[j]);
#pragma unroll
            for (int off = 8; off >= 1; off >>= 1)
                m = fmaxf(m, __shfl_xor_sync(0xffffffffu, m, off));
            float s = 0.f;
#pragma unroll
            for (int j = 0; j < 8; j++) s += expf(vals[j] - m);
#pragma unroll
            for (int off = 8; off >= 1; off >>= 1)
                s += __shfl_xor_sync(0xffffffffu, s, off);
            float lse = m + logf(s);
            if (r < M) {
#pragma unroll
                for (int jh = 0; jh < 2; jh++) {
                    int c = jh * 64 + tCol * 4;
#pragma unroll
                    for (int j = 0; j < 4; j++)
                        if (c + j < Nc)
                            out[(size_t)r * Nc + c + j] = vals[jh * 4 + j] - lse;
                }
            }
        }
    }
}

// ---------------- host launcher ---------------------------------------------
extern "C" void kernel_launch(void* const* d_in, const int* in_sizes, int n_in,
                              void* d_out, int out_size) {
    const float* x       = (const float*)d_in[0];
    const int*   e1      = (const int*)  d_in[1];
    const int*   e2      = (const int*)  d_in[2];
    const float* in_W    = (const float*)d_in[3];
    const float* in_b    = (const float*)d_in[4];
    const float* convW   = (const float*)d_in[5];
    const float* convB   = (const float*)d_in[6];
    const float* bng     = (const float*)d_in[7];
    const float* bnb     = (const float*)d_in[8];
    const float* out_W   = (const float*)d_in[9];
    const float* out_b   = (const float*)d_in[10];
    const float* layer_w = (const float*)d_in[11];
    float* out = (float*)d_out;

    float *p_h0, *p_t, *p_hist, *p_dinv1, *p_dinv2, *p_sums, *p_sqs, *p_w;
    __nv_bfloat16 *p_wth, *p_wtl, *p_inwh, *p_inwl;
    int *p_cnt1, *p_cnt2, *p_part, *p_rp1, *p_rp2, *p_cur1, *p_cur2, *p_csr1, *p_csr2;
    cudaGetSymbolAddress((void**)&p_h0, g_h0);
    cudaGetSymbolAddress((void**)&p_t, g_t);
    cudaGetSymbolAddress((void**)&p_hist, g_hist);
    cudaGetSymbolAddress((void**)&p_wth, g_wth);
    cudaGetSymbolAddress((void**)&p_wtl, g_wtl);
    cudaGetSymbolAddress((void**)&p_inwh, g_inwh);
    cudaGetSymbolAddress((void**)&p_inwl, g_inwl);
    cudaGetSymbolAddress((void**)&p_dinv1, g_dinv1);
    cudaGetSymbolAddress((void**)&p_dinv2, g_dinv2);
    cudaGetSymbolAddress((void**)&p_sums, g_sums);
    cudaGetSymbolAddress((void**)&p_sqs, g_sqs);
    cudaGetSymbolAddress((void**)&p_w, g_w);
    cudaGetSymbolAddress((void**)&p_cnt1, g_cnt1);
    cudaGetSymbolAddress((void**)&p_cnt2, g_cnt2);
    cudaGetSymbolAddress((void**)&p_part, g_part);
    cudaGetSymbolAddress((void**)&p_rp1, g_rp1);
    cudaGetSymbolAddress((void**)&p_rp2, g_rp2);
    cudaGetSymbolAddress((void**)&p_cur1, g_cur1);
    cudaGetSymbolAddress((void**)&p_cur2, g_cur2);
    cudaGetSymbolAddress((void**)&p_csr1, g_csr1);
    cudaGetSymbolAddress((void**)&p_csr2, g_csr2);

    const int outSmem = (2048 + 2048 + 8) * sizeof(float);   // 16416 B dynamic
    cudaFuncSetAttribute(mma_gemm_kernel,
                         cudaFuncAttributeMaxDynamicSharedMemorySize, MG_SMEM);
    cudaFuncSetAttribute(out_gemm_kernel,
                         cudaFuncAttributeMaxDynamicSharedMemorySize, outSmem);

    const int nThr = 256;
    const int nbE  = (E_EDGES + nThr - 1) / nThr;
    const int nbW  = (L_LAYERS * HDIM * HDIM + nThr - 1) / nThr;
    const dim3 outGrid(1, (N_NODES + BM - 1) / BM);
    const dim3 mmaGrid(2, (N_NODES + 127) / 128);
    const dim3 segGrid(NSEG, 2);
    const int aggBlocks = 1480;
    const size_t NH = (size_t)N_NODES * HDIM;

    prep_kernel<<<nbW, nThr>>>(convW, in_W, layer_w, p_wth, p_wtl,
                               p_inwh, p_inwl, p_sums, p_sqs, p_w,
                               p_cnt1, p_cnt2);

    // input FC on the tensor path: h0 = x @ in_W + in_b  (K=128, no BN/dinv)
    mma_gemm_kernel<<<mmaGrid, nThr, MG_SMEM>>>(
        x, F_INPUT, nullptr, nullptr, nullptr, nullptr, 0,
        p_inwh, p_inwl, in_b, nullptr, p_h0, N_NODES);

    hist2_kernel<<<nbE, nThr>>>(e1 + E_EDGES, e2 + E_EDGES, p_cnt1, p_cnt2);
    partial2_kernel<<<segGrid, nThr>>>(p_cnt1, p_cnt2, p_part);
    scanemit2_kernel<<<segGrid, nThr>>>(p_cnt1, p_cnt2, p_part, p_rp1, p_rp2,
                                        p_dinv1, p_dinv2, p_cur1, p_cur2);
    fill2_kernel<<<nbE, nThr>>>(e1, e2, p_cur1, p_cur2, p_csr1, p_csr2);

    for (int l = 0; l < L_LAYERS; l++) {
        const int*   rp   = (l < L_LAYERS / 2) ? p_rp1 : p_rp2;
        const int*   csr  = (l < L_LAYERS / 2) ? p_csr1 : p_csr2;
        const float* dinv = (l < L_LAYERS / 2) ? p_dinv1 : p_dinv2;
        const float* Hin  = (l == 0) ? p_h0 : p_hist + (size_t)(l - 1) * NH;
        const float* bs   = (l == 0) ? p_sums : p_sums + (l - 1) * HDIM;
        const float* bq   = (l == 0) ? p_sqs  : p_sqs + (l - 1) * HDIM;
        const float* bg   = (l == 0) ? bng : bng + (l - 1) * HDIM;
        const float* bb   = (l == 0) ? bnb : bnb + (l - 1) * HDIM;

        mma_gemm_kernel<<<mmaGrid, nThr, MG_SMEM>>>(
            Hin, HDIM, bs, bq, bg, bb, (l > 0) ? 1 : 0,
            p_wth + (size_t)l * HDIM * HDIM, p_wtl + (size_t)l * HDIM * HDIM,
            convB + l * HDIM, dinv, p_t, N_NODES);
        agg_kernel<<<aggBlocks, nThr>>>(rp, csr, dinv, p_t,
                                        p_hist + (size_t)l * NH,
                                        p_sums + l * HDIM, p_sqs + l * HDIM);
    }

    out_gemm_kernel<<<outGrid, nThr, outSmem>>>(
        p_hist, p_sums, p_sqs, bng, bnb, p_w, out_W, out_b, out, N_NODES);
}

// round 16
// speedup vs baseline: 1.0221x; 1.0103x over previous
#include <cuda_runtime.h>
#include <cuda_bf16.h>
#include <math.h>
#include <stdint.h>

#define N_NODES 50000
#define E_EDGES 800000
#define F_INPUT 128
#define HDIM    256
#define C_OUT   112
#define L_LAYERS 8
#define BN_EPS  1e-5f
#define NSEG    13
#define SEGSZ   4096

// ---------------- scratch (device globals; no allocations anywhere) --------
__device__ float g_h0[N_NODES * HDIM];                       // input FC output
__device__ float g_t[N_NODES * HDIM];                        // t' per layer
__device__ float g_hist[L_LAYERS * N_NODES * HDIM];          // raw agg out per layer
__device__ __nv_bfloat16 g_wth[L_LAYERS * HDIM * HDIM];      // convW^T hi [l][n][k]
__device__ __nv_bfloat16 g_wtl[L_LAYERS * HDIM * HDIM];      // convW^T lo
__device__ __nv_bfloat16 g_inwh[HDIM * F_INPUT];             // in_W^T hi [n][k]
__device__ __nv_bfloat16 g_inwl[HDIM * F_INPUT];             // in_W^T lo
__device__ float g_dinv1[N_NODES];
__device__ float g_dinv2[N_NODES];
__device__ float g_sums[L_LAYERS * HDIM];
__device__ float g_sqs[L_LAYERS * HDIM];
__device__ float g_w[L_LAYERS];
__device__ int g_cnt1[N_NODES];
__device__ int g_cnt2[N_NODES];
__device__ int g_part[2 * NSEG];
__device__ int g_rp1[N_NODES + 1];
__device__ int g_rp2[N_NODES + 1];
__device__ int g_cur1[N_NODES];
__device__ int g_cur2[N_NODES];
__device__ int g_csr1[E_EDGES];
__device__ int g_csr2[E_EDGES];

// ---------------- helpers ---------------------------------------------------
__device__ __forceinline__ uint32_t smem_u32(const void* p) {
    uint32_t a;
    asm("{ .reg .u64 t; cvta.to.shared.u64 t, %1; cvt.u32.u64 %0, t; }"
        : "=r"(a) : "l"(p));
    return a;
}
__device__ __forceinline__ unsigned long long pk2(float lo, float hi) {
    unsigned long long r;
    asm("mov.b64 %0, {%1, %2};" : "=l"(r) : "f"(lo), "f"(hi));
    return r;
}
__device__ __forceinline__ void upk2(float& lo, float& hi, unsigned long long v) {
    asm("mov.b64 {%0, %1}, %2;" : "=f"(lo), "=f"(hi) : "l"(v));
}
__device__ __forceinline__ void ffma2(unsigned long long& d,
                                      unsigned long long a, unsigned long long b) {
    asm("fma.rn.f32x2 %0, %1, %2, %0;" : "+l"(d) : "l"(a), "l"(b));
}
__device__ __forceinline__ void ldm_x4(uint32_t& r0, uint32_t& r1,
                                       uint32_t& r2, uint32_t& r3, uint32_t addr) {
    asm volatile("ldmatrix.sync.aligned.m8n8.x4.shared.b16 {%0,%1,%2,%3}, [%4];"
                 : "=r"(r0), "=r"(r1), "=r"(r2), "=r"(r3) : "r"(addr));
}
__device__ __forceinline__ void mma_bf16(float* d, const uint32_t* a,
                                         uint32_t b0, uint32_t b1) {
    asm volatile(
        "mma.sync.aligned.m16n8k16.row.col.f32.bf16.bf16.f32 "
        "{%0,%1,%2,%3}, {%4,%5,%6,%7}, {%8,%9}, {%0,%1,%2,%3};"
        : "+f"(d[0]), "+f"(d[1]), "+f"(d[2]), "+f"(d[3])
        : "r"(a[0]), "r"(a[1]), "r"(a[2]), "r"(a[3]), "r"(b0), "r"(b1));
}
__device__ __forceinline__ void cpa16(uint32_t dst, const void* src) {
    asm volatile("cp.async.cg.shared.global [%0], [%1], 16;"
                 :: "r"(dst), "l"(src));
}
__device__ __forceinline__ uint32_t bf2pack(__nv_bfloat16 a, __nv_bfloat16 b) {
    __nv_bfloat162 p = {a, b};
    return *(uint32_t*)&p;
}

// ---------------- prep: weight splits + zero stats/cnts + softmax(w) --------
__global__ void prep_kernel(const float* __restrict__ convW,
                            const float* __restrict__ in_W,
                            const float* __restrict__ lw,
                            __nv_bfloat16* wth, __nv_bfloat16* wtl,
                            __nv_bfloat16* inwh, __nv_bfloat16* inwl,
                            float* sums, float* sqs, float* w,
                            int* cnt1, int* cnt2) {
    int i = blockIdx.x * blockDim.x + threadIdx.x;
    if (i < L_LAYERS * HDIM) { sums[i] = 0.f; sqs[i] = 0.f; }
    if (i < N_NODES) { cnt1[i] = 0; cnt2[i] = 0; }
    if (i == 0) {
        float m = -1e30f;
        for (int l = 0; l < L_LAYERS; l++) m = fmaxf(m, lw[l]);
        float s = 0.f;
        for (int l = 0; l < L_LAYERS; l++) s += expf(lw[l] - m);
        for (int l = 0; l < L_LAYERS; l++) w[l] = expf(lw[l] - m) / s;
    }
    if (i < HDIM * F_INPUT) {   // in_W^T split: [n=256][k=128]
        int n = i / F_INPUT;
        int k = i % F_INPUT;
        float v = in_W[k * HDIM + n];
        __nv_bfloat16 hi = __float2bfloat16(v);
        inwh[i] = hi;
        inwl[i] = __float2bfloat16(v - __bfloat162float(hi));
    }
    if (i >= L_LAYERS * HDIM * HDIM) return;
    int l = i >> 16;
    int n = (i >> 8) & 255;
    int k = i & 255;
    float v = convW[(l << 16) + (k << 8) + n];
    __nv_bfloat16 hi = __float2bfloat16(v);
    wth[i] = hi;
    wtl[i] = __float2bfloat16(v - __bfloat162float(hi));
}

// ---------------- CSR build (both adjacencies per launch) -------------------
__global__ void hist2_kernel(const int* __restrict__ t1, const int* __restrict__ t2,
                             int* c1, int* c2) {
    int i = blockIdx.x * blockDim.x + threadIdx.x;
    if (i < E_EDGES) {
        atomicAdd(&c1[t1[i]], 1);
        atomicAdd(&c2[t2[i]], 1);
    }
}

// phase 1: per-segment totals. grid (NSEG, 2), 256 thr.
__global__ void partial2_kernel(const int* __restrict__ c1,
                                const int* __restrict__ c2, int* partials) {
    const int* cnt = blockIdx.y ? c2 : c1;
    int base = blockIdx.x * SEGSZ + threadIdx.x * 16;
    int s = 0;
#pragma unroll
    for (int i = 0; i < 16; i += 4) {
        int idx = base + i;
        if (idx + 3 < N_NODES) {
            int4 v = *(const int4*)(cnt + idx);
            s += v.x + v.y + v.z + v.w;
        } else {
#pragma unroll
            for (int j = 0; j < 4; j++)
                if (idx + j < N_NODES) s += cnt[idx + j];
        }
    }
    __shared__ int ws[8];
#pragma unroll
    for (int off = 16; off >= 1; off >>= 1)
        s += __shfl_xor_sync(0xffffffffu, s, off);
    if ((threadIdx.x & 31) == 0) ws[threadIdx.x >> 5] = s;
    __syncthreads();
    if (threadIdx.x == 0) {
        int t = 0;
#pragma unroll
        for (int w2 = 0; w2 < 8; w2++) t += ws[w2];
        partials[blockIdx.y * NSEG + blockIdx.x] = t;
    }
}

// phase 2: in-segment scan + emit rowptr/cursor/dinv. grid (NSEG, 2), 256 thr.
__global__ void scanemit2_kernel(const int* __restrict__ c1,
                                 const int* __restrict__ c2,
                                 const int* __restrict__ partials,
                                 int* r1, int* r2,
                                 float* d1, float* d2, int* cu1, int* cu2) {
    const int* cnt = blockIdx.y ? c2 : c1;
    int* rowptr    = blockIdx.y ? r2 : r1;
    float* dinv    = blockIdx.y ? d2 : d1;
    int* cur       = blockIdx.y ? cu2 : cu1;
    const int seg = blockIdx.x;
    int segbase = 0;
    for (int s2 = 0; s2 < seg; s2++) segbase += partials[blockIdx.y * NSEG + s2];

    const int tid = threadIdx.x, lane = tid & 31, wid = tid >> 5;
    const int base = seg * SEGSZ + tid * 16;
    int c[16];
    int loc = 0;
#pragma unroll
    for (int i = 0; i < 16; i += 4) {
        int idx = base + i;
        if (idx + 3 < N_NODES) {
            int4 v = *(const int4*)(cnt + idx);
            c[i] = v.x; c[i + 1] = v.y; c[i + 2] = v.z; c[i + 3] = v.w;
        } else {
#pragma unroll
            for (int j = 0; j < 4; j++)
                c[i + j] = (idx + j < N_NODES) ? cnt[idx + j] : 0;
        }
        loc += c[i] + c[i + 1] + c[i + 2] + c[i + 3];
    }
    int v = loc;
#pragma unroll
    for (int off = 1; off < 32; off <<= 1) {
        int n = __shfl_up_sync(0xffffffffu, v, off);
        if (lane >= off) v += n;
    }
    __shared__ int wsum[8];
    if (lane == 31) wsum[wid] = v;
    __syncthreads();
    int woff = 0;
    for (int w2 = 0; w2 < wid; w2++) woff += wsum[w2];
    int run = segbase + woff + v - loc;    // exclusive prefix
#pragma unroll
    for (int i = 0; i < 16; i++) {
        int idx = base + i;
        if (idx < N_NODES) {
            rowptr[idx] = run;
            cur[idx]    = run;
            dinv[idx]   = rsqrtf((float)c[i] + 1.0f);
            run += c[i];
        }
    }
    if (seg == NSEG - 1 && tid == 255) rowptr[N_NODES] = run;
}

__global__ void fill2_kernel(const int* __restrict__ e1, const int* __restrict__ e2,
                             int* cu1, int* cu2, int* cs1, int* cs2) {
    int i = blockIdx.x * blockDim.x + threadIdx.x;
    if (i < E_EDGES) {
        int p1 = atomicAdd(&cu1[e1[E_EDGES + i]], 1);
        cs1[p1] = e1[i];
        int p2 = atomicAdd(&cu2[e2[E_EDGES + i]], 1);
        cs2[p2] = e2[i];
    }
}

// ---------------- mma.sync GEMM, fused BN+ReLU+bf16-split A-staging --------
// C[M,256] = bf16split(relu?(bn?(Hin[M,K]))) @ B^T + bias, opt * dinv.
// CTA 128x128, warp 32x64, K chunk 32 (K = 128 or 256), double-buffered.
#define SROW 40
#define ABUF (128 * SROW * 2)                 // 10240 B per array per buffer
#define MG_SMEM (8 * ABUF + 2048)             // + bn param tables

__global__ __launch_bounds__(256, 2)
void mma_gemm_kernel(const float* __restrict__ Hin, int K,
                     const float* __restrict__ bsum, const float* __restrict__ bsq,
                     const float* __restrict__ gamma, const float* __restrict__ beta,
                     int do_bn,
                     const __nv_bfloat16* __restrict__ Bh,
                     const __nv_bfloat16* __restrict__ Bl,
                     const float* __restrict__ bias,
                     const float* __restrict__ dinv,
                     float* __restrict__ C, int M) {
    extern __shared__ char dsm[];
    float* sS  = (float*)(dsm + 8 * ABUF);
    float* sSh = sS + 256;
    const uint32_t sb = smem_u32(dsm);
    const int tid  = threadIdx.x;
    const int lane = tid & 31;
    const int wid  = tid >> 5;
    const int wm   = wid & 3;
    const int wn   = wid >> 2;
    const int brow = blockIdx.y * 128;
    const int bcol = blockIdx.x * 128;
    const int nch  = K >> 5;

    if (tid < 256) {
        if (do_bn) {
            float mu  = bsum[tid] * (1.0f / N_NODES);
            float var = bsq[tid] * (1.0f / N_NODES) - mu * mu;
            float s = gamma[tid] * rsqrtf(var + BN_EPS);
            sS[tid] = s;
            sSh[tid] = beta[tid] - mu * s;
        } else {
            sS[tid] = 1.f;
            sSh[tid] = 0.f;
        }
    }

    const int r0 = tid >> 2, r1 = r0 + 64, sg = tid & 3;
    const int gr0 = min(brow + r0, M - 1);
    const int gr1 = min(brow + r1, M - 1);
    const int wn0 = bcol + r0, wn1 = bcol + r1;
    const uint32_t d0 = (uint32_t)(r0 * SROW + sg * 8) * 2;
    const uint32_t d1 = (uint32_t)(r1 * SROW + sg * 8) * 2;

    auto issueB = [&](int c) {
        const int kb = c * 32 + sg * 8;
        const uint32_t bo = (uint32_t)(c & 1) * ABUF;
        cpa16(sb + 4 * ABUF + bo + d0, Bh + (size_t)wn0 * K + kb);
        cpa16(sb + 4 * ABUF + bo + d1, Bh + (size_t)wn1 * K + kb);
        cpa16(sb + 6 * ABUF + bo + d0, Bl + (size_t)wn0 * K + kb);
        cpa16(sb + 6 * ABUF + bo + d1, Bl + (size_t)wn1 * K + kb);
        asm volatile("cp.async.commit_group;");
    };

    float4 ar[4];
    auto loadA = [&](int c) {
        const int kb = c * 32 + sg * 8;
        ar[0] = *(const float4*)(Hin + (size_t)gr0 * K + kb);
        ar[1] = *(const float4*)(Hin + (size_t)gr0 * K + kb + 4);
        ar[2] = *(const float4*)(Hin + (size_t)gr1 * K + kb);
        ar[3] = *(const float4*)(Hin + (size_t)gr1 * K + kb + 4);
    };
    auto stageA = [&](int c) {
        const int kb = c * 32 + sg * 8;
        const uint32_t bo = (uint32_t)(c & 1) * ABUF;
        float s[8], sh[8];
#pragma unroll
        for (int j = 0; j < 8; j++) { s[j] = sS[kb + j]; sh[j] = sSh[kb + j]; }
        const float* av = (const float*)ar;
        uint32_t hiw[4], low[4];
#pragma unroll
        for (int rr = 0; rr < 2; rr++) {
            __nv_bfloat16 hb[8], lb[8];
#pragma unroll
            for (int j = 0; j < 8; j++) {
                float v = fmaf(av[rr * 8 + j], s[j], sh[j]);
                if (do_bn) v = fmaxf(v, 0.f);
                hb[j] = __float2bfloat16(v);
                lb[j] = __float2bfloat16(v - __bfloat162float(hb[j]));
            }
#pragma unroll
            for (int j = 0; j < 4; j++) {
                hiw[j] = bf2pack(hb[2 * j], hb[2 * j + 1]);
                low[j] = bf2pack(lb[2 * j], lb[2 * j + 1]);
            }
            const uint32_t dd = rr ? d1 : d0;
            *(uint4*)(dsm + bo + dd)            = *(uint4*)hiw;
            *(uint4*)(dsm + 2 * ABUF + bo + dd) = *(uint4*)low;
        }
    };

    // ldmatrix lane offsets
    const int li = lane & 7;
    const int lb_ = (lane >> 3) & 1;
    const int lc = (lane >> 4) & 1;
    uint32_t aoff[2], boff[4];
#pragma unroll
    for (int mf = 0; mf < 2; mf++)
        aoff[mf] = (uint32_t)((wm * 32 + mf * 16 + lb_ * 8 + li) * SROW + lc * 8) * 2;
#pragma unroll
    for (int nf = 0; nf < 4; nf++)
        boff[nf] = (uint32_t)((wn * 64 + nf * 16 + lc * 8 + li) * SROW + lb_ * 8) * 2;

    float acc[2][8][4];
#pragma unroll
    for (int i = 0; i < 2; i++)
#pragma unroll
        for (int j = 0; j < 8; j++)
#pragma unroll
            for (int k = 0; k < 4; k++) acc[i][j][k] = 0.f;

    issueB(0);
    loadA(0);
    __syncthreads();        // sS/sSh ready
    stageA(0);

    for (int c = 0; c < nch; c++) {
        asm volatile("cp.async.wait_group 0;" ::: "memory");
        __syncthreads();    // A(c)+B(c) visible; all MMA(c-1) reads done
        if (c + 1 < nch) { issueB(c + 1); loadA(c + 1); }

        const uint32_t bo  = (uint32_t)(c & 1) * ABUF;
        const uint32_t bAh = sb + bo;
        const uint32_t bAl = sb + 2 * ABUF + bo;
        const uint32_t bBh = sb + 4 * ABUF + bo;
        const uint32_t bBl = sb + 6 * ABUF + bo;
#pragma unroll
        for (int ks = 0; ks < 2; ks++) {
            const uint32_t kadd = ks * 32;
            uint32_t A0h[4], A1h[4], A0l[4], A1l[4];
            ldm_x4(A0h[0], A0h[1], A0h[2], A0h[3], bAh + aoff[0] + kadd);
            ldm_x4(A1h[0], A1h[1], A1h[2], A1h[3], bAh + aoff[1] + kadd);
            ldm_x4(A0l[0], A0l[1], A0l[2], A0l[3], bAl + aoff[0] + kadd);
            ldm_x4(A1l[0], A1l[1], A1l[2], A1l[3], bAl + aoff[1] + kadd);
#pragma unroll
            for (int nf = 0; nf < 4; nf++) {
                uint32_t bh[4], bl[4];
                ldm_x4(bh[0], bh[1], bh[2], bh[3], bBh + boff[nf] + kadd);
                ldm_x4(bl[0], bl[1], bl[2], bl[3], bBl + boff[nf] + kadd);
                mma_bf16(acc[0][nf * 2 + 0], A0h, bh[0], bh[1]);
                mma_bf16(acc[0][nf * 2 + 0], A0h, bl[0], bl[1]);
                mma_bf16(acc[0][nf * 2 + 0], A0l, bh[0], bh[1]);
                mma_bf16(acc[0][nf * 2 + 1], A0h, bh[2], bh[3]);
                mma_bf16(acc[0][nf * 2 + 1], A0h, bl[2], bl[3]);
                mma_bf16(acc[0][nf * 2 + 1], A0l, bh[2], bh[3]);
                mma_bf16(acc[1][nf * 2 + 0], A1h, bh[0], bh[1]);
                mma_bf16(acc[1][nf * 2 + 0], A1h, bl[0], bl[1]);
                mma_bf16(acc[1][nf * 2 + 0], A1l, bh[0], bh[1]);
                mma_bf16(acc[1][nf * 2 + 1], A1h, bh[2], bh[3]);
                mma_bf16(acc[1][nf * 2 + 1], A1h, bl[2], bl[3]);
                mma_bf16(acc[1][nf * 2 + 1], A1l, bh[2], bh[3]);
            }
        }
        if (c + 1 < nch) stageA(c + 1);
    }

    // epilogue: C[r, c] = (acc + bias[c]) * (dinv ? dinv[r] : 1)
    const int qr = lane >> 2;
    const int qc = (lane & 3) * 2;
#pragma unroll
    for (int mf = 0; mf < 2; mf++) {
        int rr0 = brow + wm * 32 + mf * 16 + qr;
        int rr1 = rr0 + 8;
        float dv0 = (rr0 < M) ? (dinv ? dinv[rr0] : 1.0f) : 0.f;
        float dv1 = (rr1 < M) ? (dinv ? dinv[rr1] : 1.0f) : 0.f;
#pragma unroll
        for (int nf = 0; nf < 8; nf++) {
            int cc = bcol + wn * 64 + nf * 8 + qc;
            float b0 = bias[cc], b1 = bias[cc + 1];
            if (rr0 < M)
                *(float2*)(C + (size_t)rr0 * HDIM + cc) =
                    make_float2((acc[mf][nf][0] + b0) * dv0,
                                (acc[mf][nf][1] + b1) * dv0);
            if (rr1 < M)
                *(float2*)(C + (size_t)rr1 * HDIM + cc) =
                    make_float2((acc[mf][nf][2] + b0) * dv1,
                                (acc[mf][nf][3] + b1) * dv1);
        }
    }
}

// ---------------- CSR aggregation + fused BN stats (index-prefetch) ---------
__global__ __launch_bounds__(256)
void agg_kernel(const int* __restrict__ rowptr, const int* __restrict__ csr,
                const float* __restrict__ dinv, const float* __restrict__ tp,
                float* __restrict__ h, float* gsum, float* gsq) {
    __shared__ float s_sum[HDIM];
    __shared__ float s_sq[HDIM];
    int tid  = threadIdx.x;
    int lane = tid & 31;
    int warp = tid >> 5;
    int gw   = blockIdx.x * 8 + warp;
    int nw   = gridDim.x * 8;

    s_sum[tid] = 0.f;
    s_sq[tid]  = 0.f;

    float ssum[8], ssq[8];
#pragma unroll
    for (int i = 0; i < 8; i++) { ssum[i] = 0.f; ssq[i] = 0.f; }

    for (int v = gw; v < N_NODES; v += nw) {
        const float4* self = (const float4*)(tp + (size_t)v * HDIM);
        float4 a0 = self[lane];
        float4 a1 = self[lane + 32];
        int beg = rowptr[v], end = rowptr[v + 1];
        int e = beg;
        // prefetch first index pair
        int n0 = 0, n1 = 0;
        if (e + 1 < end) { n0 = csr[e]; n1 = csr[e + 1]; }
        while (e + 1 < end) {
            int s0 = n0, s1 = n1;
            int en = e + 2;
            if (en + 1 < end) { n0 = csr[en]; n1 = csr[en + 1]; }  // overlap w/ rows
            const float4* r0 = (const float4*)(tp + (size_t)s0 * HDIM);
            const float4* r1 = (const float4*)(tp + (size_t)s1 * HDIM);
            float4 v00 = r0[lane], v01 = r0[lane + 32];
            float4 v10 = r1[lane], v11 = r1[lane + 32];
            a0.x += v00.x + v10.x; a0.y += v00.y + v10.y;
            a0.z += v00.z + v10.z; a0.w += v00.w + v10.w;
            a1.x += v01.x + v11.x; a1.y += v01.y + v11.y;
            a1.z += v01.z + v11.z; a1.w += v01.w + v11.w;
            e = en;
        }
        if (e < end) {
            int s0 = csr[e];
            const float4* r0 = (const float4*)(tp + (size_t)s0 * HDIM);
            float4 v00 = r0[lane], v01 = r0[lane + 32];
            a0.x += v00.x; a0.y += v00.y; a0.z += v00.z; a0.w += v00.w;
            a1.x += v01.x; a1.y += v01.y; a1.z += v01.z; a1.w += v01.w;
        }
        float dv = dinv[v];
        a0.x *= dv; a0.y *= dv; a0.z *= dv; a0.w *= dv;
        a1.x *= dv; a1.y *= dv; a1.z *= dv; a1.w *= dv;
        float4* hrow = (float4*)(h + (size_t)v * HDIM);
        hrow[lane]      = a0;
        hrow[lane + 32] = a1;
        ssum[0] += a0.x; ssum[1] += a0.y; ssum[2] += a0.z; ssum[3] += a0.w;
        ssum[4] += a1.x; ssum[5] += a1.y; ssum[6] += a1.z; ssum[7] += a1.w;
        ssq[0] += a0.x * a0.x; ssq[1] += a0.y * a0.y;
        ssq[2] += a0.z * a0.z; ssq[3] += a0.w * a0.w;
        ssq[4] += a1.x * a1.x; ssq[5] += a1.y * a1.y;
        ssq[6] += a1.z * a1.z; ssq[7] += a1.w * a1.w;
    }
    __syncthreads();
#pragma unroll
    for (int k = 0; k < 4; k++) {
        atomicAdd(&s_sum[lane * 4 + k], ssum[k]);
        atomicAdd(&s_sum[128 + lane * 4 + k], ssum[4 + k]);
        atomicAdd(&s_sq[lane * 4 + k], ssq[k]);
        atomicAdd(&s_sq[128 + lane * 4 + k], ssq[4 + k]);
    }
    __syncthreads();
    atomicAdd(&gsum[tid], s_sum[tid]);
    atomicAdd(&gsq[tid], s_sq[tid]);
}

// ---------------- output FC + fused combine + log-softmax -------------------
#define BM 128
#define BN 128
#define BK 16
__global__ __launch_bounds__(256, 2)
void out_gemm_kernel(const float* __restrict__ hist,
                     const float* __restrict__ sums, const float* __restrict__ sqs,
                     const float* __restrict__ gamma, const float* __restrict__ beta,
                     const float* __restrict__ w,
                     const float* __restrict__ B,
                     const float* __restrict__ bias, float* __restrict__ out,
                     int M) {
    const int Nc = C_OUT;
    const int K = HDIM;
    const size_t NH = (size_t)N_NODES * HDIM;
    __shared__ float As[2][BK][BM + 4];
    __shared__ float Bs[2][BK][BN];
    extern __shared__ float tbl[];
    float* tS  = tbl;          // [8][256]
    float* tSh = tbl + 2048;   // [8][256]
    float* tw  = tbl + 4096;   // [8]

    const int tid  = threadIdx.x;
    const int tRow = tid >> 4;
    const int tCol = tid & 15;
    const int brow = blockIdx.y * BM;
    const int am0 = tid >> 2;
    const int am1 = (tid + 256) >> 2;
    const int ak  = (tid & 3) * 4;
    const int arow0 = min(brow + am0, M - 1);
    const int arow1 = min(brow + am1, M - 1);
    const int bk0 = tid >> 5;
    const int bk1 = bk0 + 8;
    const int bnx = (tid & 31) * 4;
    const bool bok = (bnx + 3) < Nc;
    const int bcl  = bok ? bnx : 0;

    if (tid < 256) {
#pragma unroll
        for (int l = 0; l < L_LAYERS; l++) {
            float mu  = sums[l * HDIM + tid] * (1.0f / N_NODES);
            float var = sqs[l * HDIM + tid] * (1.0f / N_NODES) - mu * mu;
            float s = gamma[l * HDIM + tid] * rsqrtf(var + BN_EPS);
            tS[l * 256 + tid] = s;
            tSh[l * 256 + tid] = beta[l * HDIM + tid] - mu * s;
        }
    }
    if (tid < L_LAYERS) tw[tid] = w[tid];
    __syncthreads();

    auto combineA = [&](int row, int kc) -> float4 {
        float4 a = make_float4(0.f, 0.f, 0.f, 0.f);
#pragma unroll
        for (int l = 0; l < L_LAYERS; l++) {
            float4 v  = *(const float4*)(hist + (size_t)l * NH + (size_t)row * HDIM + kc);
            float4 s  = *(const float4*)(tS + l * 256 + kc);
            float4 sh = *(const float4*)(tSh + l * 256 + kc);
            float wl = tw[l];
            a.x = fmaf(wl, fmaxf(fmaf(v.x, s.x, sh.x), 0.f), a.x);
            a.y = fmaf(wl, fmaxf(fmaf(v.y, s.y, sh.y), 0.f), a.y);
            a.z = fmaf(wl, fmaxf(fmaf(v.z, s.z, sh.z), 0.f), a.z);
            a.w = fmaf(wl, fmaxf(fmaf(v.w, s.w, sh.w), 0.f), a.w);
        }
        return a;
    };

    unsigned long long acc[8][4];
#pragma unroll
    for (int i = 0; i < 8; i++)
#pragma unroll
        for (int j = 0; j < 4; j++) acc[i][j] = 0ull;

    float4 aR0, aR1, bR0, bR1;
    const float4 z4 = make_float4(0.f, 0.f, 0.f, 0.f);
    aR0 = combineA(arow0, ak);
    aR1 = combineA(arow1, ak);
    bR0 = bok ? *(const float4*)(B + (size_t)bk0 * Nc + bcl) : z4;
    bR1 = bok ? *(const float4*)(B + (size_t)bk1 * Nc + bcl) : z4;
    As[0][ak + 0][am0] = aR0.x; As[0][ak + 1][am0] = aR0.y;
    As[0][ak + 2][am0] = aR0.z; As[0][ak + 3][am0] = aR0.w;
    As[0][ak + 0][am1] = aR1.x; As[0][ak + 1][am1] = aR1.y;
    As[0][ak + 2][am1] = aR1.z; As[0][ak + 3][am1] = aR1.w;
    *(float4*)&Bs[0][bk0][bnx] = bR0;
    *(float4*)&Bs[0][bk1][bnx] = bR1;
    __syncthreads();

    const int nt = K / BK;
    for (int kt = 0; kt < nt; kt++) {
        const int buf = kt & 1;
        const int nxt = kt + 1;
        if (nxt < nt) {
            const int k0 = nxt * BK;
            aR0 = combineA(arow0, k0 + ak);
            aR1 = combineA(arow1, k0 + ak);
            bR0 = bok ? *(const float4*)(B + (size_t)(k0 + bk0) * Nc + bcl) : z4;
            bR1 = bok ? *(const float4*)(B + (size_t)(k0 + bk1) * Nc + bcl) : z4;
        }
#pragma unroll
        for (int k = 0; k < BK; k++) {
            float4 a0 = *(const float4*)&As[buf][k][tRow * 4];
            float4 a1 = *(const float4*)&As[buf][k][64 + tRow * 4];
            float4 b0 = *(const float4*)&Bs[buf][k][tCol * 4];
            float4 b1 = *(const float4*)&Bs[buf][k][64 + tCol * 4];
            unsigned long long bb[4] = {pk2(b0.x, b0.y), pk2(b0.z, b0.w),
                                        pk2(b1.x, b1.y), pk2(b1.z, b1.w)};
            float av[8] = {a0.x, a0.y, a0.z, a0.w, a1.x, a1.y, a1.z, a1.w};
#pragma unroll
            for (int i = 0; i < 8; i++) {
                unsigned long long ap = pk2(av[i], av[i]);
#pragma unroll
                for (int j = 0; j < 4; j++) ffma2(acc[i][j], ap, bb[j]);
            }
        }
        if (nxt < nt) {
            const int nb = nxt & 1;
            As[nb][ak + 0][am0] = aR0.x; As[nb][ak + 1][am0] = aR0.y;
            As[nb][ak + 2][am0] = aR0.z; As[nb][ak + 3][am0] = aR0.w;
            As[nb][ak + 0][am1] = aR1.x; As[nb][ak + 1][am1] = aR1.y;
            As[nb][ak + 2][am1] = aR1.z; As[nb][ak + 3][am1] = aR1.w;
            *(float4*)&Bs[nb][bk0][bnx] = bR0;
            *(float4*)&Bs[nb][bk1][bnx] = bR1;
        }
        __syncthreads();
    }

    // fused log-softmax epilogue
#pragma unroll
    for (int ih = 0; ih < 2; ih++) {
#pragma unroll
        for (int i = 0; i < 4; i++) {
            int r = brow + ih * 64 + tRow * 4 + i;
            float vals[8];
#pragma unroll
            for (int jh = 0; jh < 2; jh++) {
                float e0, e1, e2, e3;
                upk2(e0, e1, acc[ih * 4 + i][jh * 2 + 0]);
                upk2(e2, e3, acc[ih * 4 + i][jh * 2 + 1]);
                int c = jh * 64 + tCol * 4;
                vals[jh * 4 + 0] = (c + 0 < Nc) ? e0 + bias[c + 0] : -1e30f;
                vals[jh * 4 + 1] = (c + 1 < Nc) ? e1 + bias[c + 1] : -1e30f;
                vals[jh * 4 + 2] = (c + 2 < Nc) ? e2 + bias[c + 2] : -1e30f;
                vals[jh * 4 + 3] = (c + 3 < Nc) ? e3 + bias[c + 3] : -1e30f;
            }
            float m = vals[0];
#pragma unroll
            for (int j = 1; j < 8; j++) m = fmaxf(m, vals[j]);
#pragma unroll
            for (int off = 8; off >= 1; off >>= 1)
                m = fmaxf(m, __shfl_xor_sync(0xffffffffu, m, off));
            float s = 0.f;
#pragma unroll
            for (int j = 0; j < 8; j++) s += expf(vals[j] - m);
#pragma unroll
            for (int off = 8; off >= 1; off >>= 1)
                s += __shfl_xor_sync(0xffffffffu, s, off);
            float lse = m + logf(s);
            if (r < M) {
#pragma unroll
                for (int jh = 0; jh < 2; jh++) {
                    int c = jh * 64 + tCol * 4;
#pragma unroll
                    for (int j = 0; j < 4; j++)
                        if (c + j < Nc)
                            out[(size_t)r * Nc + c + j] = vals[jh * 4 + j] - lse;
                }
            }
        }
    }
}

// ---------------- host launcher ---------------------------------------------
extern "C" void kernel_launch(void* const* d_in, const int* in_sizes, int n_in,
                              void* d_out, int out_size) {
    const float* x       = (const float*)d_in[0];
    const int*   e1      = (const int*)  d_in[1];
    const int*   e2      = (const int*)  d_in[2];
    const float* in_W    = (const float*)d_in[3];
    const float* in_b    = (const float*)d_in[4];
    const float* convW   = (const float*)d_in[5];
    const float* convB   = (const float*)d_in[6];
    const float* bng     = (const float*)d_in[7];
    const float* bnb     = (const float*)d_in[8];
    const float* out_W   = (const float*)d_in[9];
    const float* out_b   = (const float*)d_in[10];
    const float* layer_w = (const float*)d_in[11];
    float* out = (float*)d_out;

    float *p_h0, *p_t, *p_hist, *p_dinv1, *p_dinv2, *p_sums, *p_sqs, *p_w;
    __nv_bfloat16 *p_wth, *p_wtl, *p_inwh, *p_inwl;
    int *p_cnt1, *p_cnt2, *p_part, *p_rp1, *p_rp2, *p_cur1, *p_cur2, *p_csr1, *p_csr2;
    cudaGetSymbolAddress((void**)&p_h0, g_h0);
    cudaGetSymbolAddress((void**)&p_t, g_t);
    cudaGetSymbolAddress((void**)&p_hist, g_hist);
    cudaGetSymbolAddress((void**)&p_wth, g_wth);
    cudaGetSymbolAddress((void**)&p_wtl, g_wtl);
    cudaGetSymbolAddress((void**)&p_inwh, g_inwh);
    cudaGetSymbolAddress((void**)&p_inwl, g_inwl);
    cudaGetSymbolAddress((void**)&p_dinv1, g_dinv1);
    cudaGetSymbolAddress((void**)&p_dinv2, g_dinv2);
    cudaGetSymbolAddress((void**)&p_sums, g_sums);
    cudaGetSymbolAddress((void**)&p_sqs, g_sqs);
    cudaGetSymbolAddress((void**)&p_w, g_w);
    cudaGetSymbolAddress((void**)&p_cnt1, g_cnt1);
    cudaGetSymbolAddress((void**)&p_cnt2, g_cnt2);
    cudaGetSymbolAddress((void**)&p_part, g_part);
    cudaGetSymbolAddress((void**)&p_rp1, g_rp1);
    cudaGetSymbolAddress((void**)&p_rp2, g_rp2);
    cudaGetSymbolAddress((void**)&p_cur1, g_cur1);
    cudaGetSymbolAddress((void**)&p_cur2, g_cur2);
    cudaGetSymbolAddress((void**)&p_csr1, g_csr1);
    cudaGetSymbolAddress((void**)&p_csr2, g_csr2);

    const int outSmem = (2048 + 2048 + 8) * sizeof(float);   // 16416 B dynamic
    cudaFuncSetAttribute(mma_gemm_kernel,
                         cudaFuncAttributeMaxDynamicSharedMemorySize, MG_SMEM);
    cudaFuncSetAttribute(out_gemm_kernel,
                         cudaFuncAttributeMaxDynamicSharedMemorySize, outSmem);

    const int nThr = 256;
    const int nbE  = (E_EDGES + nThr - 1) / nThr;
    const int nbW  = (L_LAYERS * HDIM * HDIM + nThr - 1) / nThr;
    const dim3 outGrid(1, (N_NODES + BM - 1) / BM);
    const dim3 mmaGrid(2, (N_NODES + 127) / 128);
    const dim3 segGrid(NSEG, 2);
    const int aggBlocks = 1480;
    const size_t NH = (size_t)N_NODES * HDIM;

    prep_kernel<<<nbW, nThr>>>(convW, in_W, layer_w, p_wth, p_wtl,
                               p_inwh, p_inwl, p_sums, p_sqs, p_w,
                               p_cnt1, p_cnt2);

    // input FC on the tensor path: h0 = x @ in_W + in_b  (K=128, no BN/dinv)
    mma_gemm_kernel<<<mmaGrid, nThr, MG_SMEM>>>(
        x, F_INPUT, nullptr, nullptr, nullptr, nullptr, 0,
        p_inwh, p_inwl, in_b, nullptr, p_h0, N_NODES);

    hist2_kernel<<<nbE, nThr>>>(e1 + E_EDGES, e2 + E_EDGES, p_cnt1, p_cnt2);
    partial2_kernel<<<segGrid, nThr>>>(p_cnt1, p_cnt2, p_part);
    scanemit2_kernel<<<segGrid, nThr>>>(p_cnt1, p_cnt2, p_part, p_rp1, p_rp2,
                                        p_dinv1, p_dinv2, p_cur1, p_cur2);
    fill2_kernel<<<nbE, nThr>>>(e1, e2, p_cur1, p_cur2, p_csr1, p_csr2);

    for (int l = 0; l < L_LAYERS; l++) {
        const int*   rp   = (l < L_LAYERS / 2) ? p_rp1 : p_rp2;
        const int*   csr  = (l < L_LAYERS / 2) ? p_csr1 : p_csr2;
        const float* dinv = (l < L_LAYERS / 2) ? p_dinv1 : p_dinv2;
        const float* Hin  = (l == 0) ? p_h0 : p_hist + (size_t)(l - 1) * NH;
        const float* bs   = (l == 0) ? p_sums : p_sums + (l - 1) * HDIM;
        const float* bq   = (l == 0) ? p_sqs  : p_sqs + (l - 1) * HDIM;
        const float* bg   = (l == 0) ? bng : bng + (l - 1) * HDIM;
        const float* bb   = (l == 0) ? bnb : bnb + (l - 1) * HDIM;

        mma_gemm_kernel<<<mmaGrid, nThr, MG_SMEM>>>(
            Hin, HDIM, bs, bq, bg, bb, (l > 0) ? 1 : 0,
            p_wth + (size_t)l * HDIM * HDIM, p_wtl + (size_t)l * HDIM * HDIM,
            convB + l * HDIM, dinv, p_t, N_NODES);
        agg_kernel<<<aggBlocks, nThr>>>(rp, csr, dinv, p_t,
                                        p_hist + (size_t)l * NH,
                                        p_sums + l * HDIM, p_sqs + l * HDIM);
    }

    out_gemm_kernel<<<outGrid, nThr, outSmem>>>(
        p_hist, p_sums, p_sqs, bng, bnb, p_w, out_W, out_b, out, N_NODES);
}

// round 17
// speedup vs baseline: 1.0234x; 1.0012x over previous
#include <cuda_runtime.h>
#include <cuda_bf16.h>
#include <math.h>
#include <stdint.h>

#define N_NODES 50000
#define E_EDGES 800000
#define F_INPUT 128
#define HDIM    256
#define C_OUT   112
#define L_LAYERS 8
#define BN_EPS  1e-5f
#define NSEG    13
#define SEGSZ   4096

// ---------------- scratch (device globals; no allocations anywhere) --------
__device__ float g_h0[N_NODES * HDIM];                       // input FC output
__device__ float g_t[N_NODES * HDIM];                        // t' per layer
__device__ float g_hist[L_LAYERS * N_NODES * HDIM];          // raw agg out per layer
__device__ __nv_bfloat16 g_wth[L_LAYERS * HDIM * HDIM];      // convW^T hi [l][n][k]
__device__ __nv_bfloat16 g_wtl[L_LAYERS * HDIM * HDIM];      // convW^T lo
__device__ __nv_bfloat16 g_inwh[HDIM * F_INPUT];             // in_W^T hi [n][k]
__device__ __nv_bfloat16 g_inwl[HDIM * F_INPUT];             // in_W^T lo
__device__ float g_dinv1[N_NODES];
__device__ float g_dinv2[N_NODES];
__device__ float g_sums[L_LAYERS * HDIM];
__device__ float g_sqs[L_LAYERS * HDIM];
__device__ float g_w[L_LAYERS];
__device__ int g_cnt1[N_NODES];
__device__ int g_cnt2[N_NODES];
__device__ int g_part[2 * NSEG];
__device__ int g_rp1[N_NODES + 1];
__device__ int g_rp2[N_NODES + 1];
__device__ int g_cur1[N_NODES];
__device__ int g_cur2[N_NODES];
__device__ int g_csr1[E_EDGES];
__device__ int g_csr2[E_EDGES];

// ---------------- helpers ---------------------------------------------------
__device__ __forceinline__ uint32_t smem_u32(const void* p) {
    uint32_t a;
    asm("{ .reg .u64 t; cvta.to.shared.u64 t, %1; cvt.u32.u64 %0, t; }"
        : "=r"(a) : "l"(p));
    return a;
}
__device__ __forceinline__ unsigned long long pk2(float lo, float hi) {
    unsigned long long r;
    asm("mov.b64 %0, {%1, %2};" : "=l"(r) : "f"(lo), "f"(hi));
    return r;
}
__device__ __forceinline__ void upk2(float& lo, float& hi, unsigned long long v) {
    asm("mov.b64 {%0, %1}, %2;" : "=f"(lo), "=f"(hi) : "l"(v));
}
__device__ __forceinline__ void ffma2(unsigned long long& d,
                                      unsigned long long a, unsigned long long b) {
    asm("fma.rn.f32x2 %0, %1, %2, %0;" : "+l"(d) : "l"(a), "l"(b));
}
__device__ __forceinline__ void ldm_x4(uint32_t& r0, uint32_t& r1,
                                       uint32_t& r2, uint32_t& r3, uint32_t addr) {
    asm volatile("ldmatrix.sync.aligned.m8n8.x4.shared.b16 {%0,%1,%2,%3}, [%4];"
                 : "=r"(r0), "=r"(r1), "=r"(r2), "=r"(r3) : "r"(addr));
}
__device__ __forceinline__ void mma_bf16(float* d, const uint32_t* a,
                                         uint32_t b0, uint32_t b1) {
    asm volatile(
        "mma.sync.aligned.m16n8k16.row.col.f32.bf16.bf16.f32 "
        "{%0,%1,%2,%3}, {%4,%5,%6,%7}, {%8,%9}, {%0,%1,%2,%3};"
        : "+f"(d[0]), "+f"(d[1]), "+f"(d[2]), "+f"(d[3])
        : "r"(a[0]), "r"(a[1]), "r"(a[2]), "r"(a[3]), "r"(b0), "r"(b1));
}
__device__ __forceinline__ void cpa16(uint32_t dst, const void* src) {
    asm volatile("cp.async.cg.shared.global [%0], [%1], 16;"
                 :: "r"(dst), "l"(src));
}
__device__ __forceinline__ uint32_t bf2pack(__nv_bfloat16 a, __nv_bfloat16 b) {
    __nv_bfloat162 p = {a, b};
    return *(uint32_t*)&p;
}

// ---------------- prep: weight splits + zero stats/cnts + softmax(w) --------
__global__ void prep_kernel(const float* __restrict__ convW,
                            const float* __restrict__ in_W,
                            const float* __restrict__ lw,
                            __nv_bfloat16* wth, __nv_bfloat16* wtl,
                            __nv_bfloat16* inwh, __nv_bfloat16* inwl,
                            float* sums, float* sqs, float* w,
                            int* cnt1, int* cnt2) {
    int i = blockIdx.x * blockDim.x + threadIdx.x;
    if (i < L_LAYERS * HDIM) { sums[i] = 0.f; sqs[i] = 0.f; }
    if (i < N_NODES) { cnt1[i] = 0; cnt2[i] = 0; }
    if (i == 0) {
        float m = -1e30f;
        for (int l = 0; l < L_LAYERS; l++) m = fmaxf(m, lw[l]);
        float s = 0.f;
        for (int l = 0; l < L_LAYERS; l++) s += expf(lw[l] - m);
        for (int l = 0; l < L_LAYERS; l++) w[l] = expf(lw[l] - m) / s;
    }
    if (i < HDIM * F_INPUT) {   // in_W^T split: [n=256][k=128]
        int n = i / F_INPUT;
        int k = i % F_INPUT;
        float v = in_W[k * HDIM + n];
        __nv_bfloat16 hi = __float2bfloat16(v);
        inwh[i] = hi;
        inwl[i] = __float2bfloat16(v - __bfloat162float(hi));
    }
    if (i >= L_LAYERS * HDIM * HDIM) return;
    int l = i >> 16;
    int n = (i >> 8) & 255;
    int k = i & 255;
    float v = convW[(l << 16) + (k << 8) + n];
    __nv_bfloat16 hi = __float2bfloat16(v);
    wth[i] = hi;
    wtl[i] = __float2bfloat16(v - __bfloat162float(hi));
}

// ---------------- CSR build (both adjacencies per launch) -------------------
// 2 edges per thread, int2 index loads.
__global__ void hist2_kernel(const int* __restrict__ t1, const int* __restrict__ t2,
                             int* c1, int* c2) {
    int i = (blockIdx.x * blockDim.x + threadIdx.x) * 2;
    if (i + 1 < E_EDGES) {
        int2 a = *(const int2*)(t1 + i);
        int2 b = *(const int2*)(t2 + i);
        atomicAdd(&c1[a.x], 1);
        atomicAdd(&c1[a.y], 1);
        atomicAdd(&c2[b.x], 1);
        atomicAdd(&c2[b.y], 1);
    } else if (i < E_EDGES) {
        atomicAdd(&c1[t1[i]], 1);
        atomicAdd(&c2[t2[i]], 1);
    }
}

// phase 1: per-segment totals. grid (NSEG, 2), 256 thr.
__global__ void partial2_kernel(const int* __restrict__ c1,
                                const int* __restrict__ c2, int* partials) {
    const int* cnt = blockIdx.y ? c2 : c1;
    int base = blockIdx.x * SEGSZ + threadIdx.x * 16;
    int s = 0;
#pragma unroll
    for (int i = 0; i < 16; i += 4) {
        int idx = base + i;
        if (idx + 3 < N_NODES) {
            int4 v = *(const int4*)(cnt + idx);
            s += v.x + v.y + v.z + v.w;
        } else {
#pragma unroll
            for (int j = 0; j < 4; j++)
                if (idx + j < N_NODES) s += cnt[idx + j];
        }
    }
    __shared__ int ws[8];
#pragma unroll
    for (int off = 16; off >= 1; off >>= 1)
        s += __shfl_xor_sync(0xffffffffu, s, off);
    if ((threadIdx.x & 31) == 0) ws[threadIdx.x >> 5] = s;
    __syncthreads();
    if (threadIdx.x == 0) {
        int t = 0;
#pragma unroll
        for (int w2 = 0; w2 < 8; w2++) t += ws[w2];
        partials[blockIdx.y * NSEG + blockIdx.x] = t;
    }
}

// phase 2: in-segment scan + emit rowptr/cursor/dinv. grid (NSEG, 2), 256 thr.
__global__ void scanemit2_kernel(const int* __restrict__ c1,
                                 const int* __restrict__ c2,
                                 const int* __restrict__ partials,
                                 int* r1, int* r2,
                                 float* d1, float* d2, int* cu1, int* cu2) {
    const int* cnt = blockIdx.y ? c2 : c1;
    int* rowptr    = blockIdx.y ? r2 : r1;
    float* dinv    = blockIdx.y ? d2 : d1;
    int* cur       = blockIdx.y ? cu2 : cu1;
    const int seg = blockIdx.x;
    int segbase = 0;
    for (int s2 = 0; s2 < seg; s2++) segbase += partials[blockIdx.y * NSEG + s2];

    const int tid = threadIdx.x, lane = tid & 31, wid = tid >> 5;
    const int base = seg * SEGSZ + tid * 16;
    int c[16];
    int loc = 0;
#pragma unroll
    for (int i = 0; i < 16; i += 4) {
        int idx = base + i;
        if (idx + 3 < N_NODES) {
            int4 v = *(const int4*)(cnt + idx);
            c[i] = v.x; c[i + 1] = v.y; c[i + 2] = v.z; c[i + 3] = v.w;
        } else {
#pragma unroll
            for (int j = 0; j < 4; j++)
                c[i + j] = (idx + j < N_NODES) ? cnt[idx + j] : 0;
        }
        loc += c[i] + c[i + 1] + c[i + 2] + c[i + 3];
    }
    int v = loc;
#pragma unroll
    for (int off = 1; off < 32; off <<= 1) {
        int n = __shfl_up_sync(0xffffffffu, v, off);
        if (lane >= off) v += n;
    }
    __shared__ int wsum[8];
    if (lane == 31) wsum[wid] = v;
    __syncthreads();
    int woff = 0;
    for (int w2 = 0; w2 < wid; w2++) woff += wsum[w2];
    int run = segbase + woff + v - loc;    // exclusive prefix
#pragma unroll
    for (int i = 0; i < 16; i++) {
        int idx = base + i;
        if (idx < N_NODES) {
            rowptr[idx] = run;
            cur[idx]    = run;
            dinv[idx]   = rsqrtf((float)c[i] + 1.0f);
            run += c[i];
        }
    }
    if (seg == NSEG - 1 && tid == 255) rowptr[N_NODES] = run;
}

// 2 edges per thread, int2 index loads.
__global__ void fill2_kernel(const int* __restrict__ e1, const int* __restrict__ e2,
                             int* cu1, int* cu2, int* cs1, int* cs2) {
    int i = (blockIdx.x * blockDim.x + threadIdx.x) * 2;
    if (i + 1 < E_EDGES) {
        int2 s1v = *(const int2*)(e1 + i);
        int2 t1v = *(const int2*)(e1 + E_EDGES + i);
        int2 s2v = *(const int2*)(e2 + i);
        int2 t2v = *(const int2*)(e2 + E_EDGES + i);
        int p0 = atomicAdd(&cu1[t1v.x], 1);
        cs1[p0] = s1v.x;
        int p1 = atomicAdd(&cu1[t1v.y], 1);
        cs1[p1] = s1v.y;
        int q0 = atomicAdd(&cu2[t2v.x], 1);
        cs2[q0] = s2v.x;
        int q1 = atomicAdd(&cu2[t2v.y], 1);
        cs2[q1] = s2v.y;
    } else if (i < E_EDGES) {
        int p0 = atomicAdd(&cu1[e1[E_EDGES + i]], 1);
        cs1[p0] = e1[i];
        int q0 = atomicAdd(&cu2[e2[E_EDGES + i]], 1);
        cs2[q0] = e2[i];
    }
}

// ---------------- mma.sync GEMM, fused BN+ReLU+bf16-split A-staging --------
// C[M,256] = bf16split(relu?(bn?(Hin[M,K]))) @ B^T + bias, opt * dinv.
// CTA 128x128, warp 32x64, K chunk 32 (K = 128 or 256), double-buffered.
#define SROW 40
#define ABUF (128 * SROW * 2)                 // 10240 B per array per buffer
#define MG_SMEM (8 * ABUF + 2048)             // + bn param tables

__global__ __launch_bounds__(256, 2)
void mma_gemm_kernel(const float* __restrict__ Hin, int K,
                     const float* __restrict__ bsum, const float* __restrict__ bsq,
                     const float* __restrict__ gamma, const float* __restrict__ beta,
                     int do_bn,
                     const __nv_bfloat16* __restrict__ Bh,
                     const __nv_bfloat16* __restrict__ Bl,
                     const float* __restrict__ bias,
                     const float* __restrict__ dinv,
                     float* __restrict__ C, int M) {
    extern __shared__ char dsm[];
    float* sS  = (float*)(dsm + 8 * ABUF);
    float* sSh = sS + 256;
    const uint32_t sb = smem_u32(dsm);
    const int tid  = threadIdx.x;
    const int lane = tid & 31;
    const int wid  = tid >> 5;
    const int wm   = wid & 3;
    const int wn   = wid >> 2;
    const int brow = blockIdx.y * 128;
    const int bcol = blockIdx.x * 128;
    const int nch  = K >> 5;

    if (tid < 256) {
        if (do_bn) {
            float mu  = bsum[tid] * (1.0f / N_NODES);
            float var = bsq[tid] * (1.0f / N_NODES) - mu * mu;
            float s = gamma[tid] * rsqrtf(var + BN_EPS);
            sS[tid] = s;
            sSh[tid] = beta[tid] - mu * s;
        } else {
            sS[tid] = 1.f;
            sSh[tid] = 0.f;
        }
    }

    const int r0 = tid >> 2, r1 = r0 + 64, sg = tid & 3;
    const int gr0 = min(brow + r0, M - 1);
    const int gr1 = min(brow + r1, M - 1);
    const int wn0 = bcol + r0, wn1 = bcol + r1;
    const uint32_t d0 = (uint32_t)(r0 * SROW + sg * 8) * 2;
    const uint32_t d1 = (uint32_t)(r1 * SROW + sg * 8) * 2;

    auto issueB = [&](int c) {
        const int kb = c * 32 + sg * 8;
        const uint32_t bo = (uint32_t)(c & 1) * ABUF;
        cpa16(sb + 4 * ABUF + bo + d0, Bh + (size_t)wn0 * K + kb);
        cpa16(sb + 4 * ABUF + bo + d1, Bh + (size_t)wn1 * K + kb);
        cpa16(sb + 6 * ABUF + bo + d0, Bl + (size_t)wn0 * K + kb);
        cpa16(sb + 6 * ABUF + bo + d1, Bl + (size_t)wn1 * K + kb);
        asm volatile("cp.async.commit_group;");
    };

    float4 ar[4];
    auto loadA = [&](int c) {
        const int kb = c * 32 + sg * 8;
        ar[0] = *(const float4*)(Hin + (size_t)gr0 * K + kb);
        ar[1] = *(const float4*)(Hin + (size_t)gr0 * K + kb + 4);
        ar[2] = *(const float4*)(Hin + (size_t)gr1 * K + kb);
        ar[3] = *(const float4*)(Hin + (size_t)gr1 * K + kb + 4);
    };
    auto stageA = [&](int c) {
        const int kb = c * 32 + sg * 8;
        const uint32_t bo = (uint32_t)(c & 1) * ABUF;
        float s[8], sh[8];
#pragma unroll
        for (int j = 0; j < 8; j++) { s[j] = sS[kb + j]; sh[j] = sSh[kb + j]; }
        const float* av = (const float*)ar;
        uint32_t hiw[4], low[4];
#pragma unroll
        for (int rr = 0; rr < 2; rr++) {
            __nv_bfloat16 hb[8], lb[8];
#pragma unroll
            for (int j = 0; j < 8; j++) {
                float v = fmaf(av[rr * 8 + j], s[j], sh[j]);
                if (do_bn) v = fmaxf(v, 0.f);
                hb[j] = __float2bfloat16(v);
                lb[j] = __float2bfloat16(v - __bfloat162float(hb[j]));
            }
#pragma unroll
            for (int j = 0; j < 4; j++) {
                hiw[j] = bf2pack(hb[2 * j], hb[2 * j + 1]);
                low[j] = bf2pack(lb[2 * j], lb[2 * j + 1]);
            }
            const uint32_t dd = rr ? d1 : d0;
            *(uint4*)(dsm + bo + dd)            = *(uint4*)hiw;
            *(uint4*)(dsm + 2 * ABUF + bo + dd) = *(uint4*)low;
        }
    };

    // ldmatrix lane offsets
    const int li = lane & 7;
    const int lb_ = (lane >> 3) & 1;
    const int lc = (lane >> 4) & 1;
    uint32_t aoff[2], boff[4];
#pragma unroll
    for (int mf = 0; mf < 2; mf++)
        aoff[mf] = (uint32_t)((wm * 32 + mf * 16 + lb_ * 8 + li) * SROW + lc * 8) * 2;
#pragma unroll
    for (int nf = 0; nf < 4; nf++)
        boff[nf] = (uint32_t)((wn * 64 + nf * 16 + lc * 8 + li) * SROW + lb_ * 8) * 2;

    float acc[2][8][4];
#pragma unroll
    for (int i = 0; i < 2; i++)
#pragma unroll
        for (int j = 0; j < 8; j++)
#pragma unroll
            for (int k = 0; k < 4; k++) acc[i][j][k] = 0.f;

    issueB(0);
    loadA(0);
    __syncthreads();        // sS/sSh ready
    stageA(0);

    for (int c = 0; c < nch; c++) {
        asm volatile("cp.async.wait_group 0;" ::: "memory");
        __syncthreads();    // A(c)+B(c) visible; all MMA(c-1) reads done
        if (c + 1 < nch) { issueB(c + 1); loadA(c + 1); }

        const uint32_t bo  = (uint32_t)(c & 1) * ABUF;
        const uint32_t bAh = sb + bo;
        const uint32_t bAl = sb + 2 * ABUF + bo;
        const uint32_t bBh = sb + 4 * ABUF + bo;
        const uint32_t bBl = sb + 6 * ABUF + bo;
#pragma unroll
        for (int ks = 0; ks < 2; ks++) {
            const uint32_t kadd = ks * 32;
            uint32_t A0h[4], A1h[4], A0l[4], A1l[4];
            ldm_x4(A0h[0], A0h[1], A0h[2], A0h[3], bAh + aoff[0] + kadd);
            ldm_x4(A1h[0], A1h[1], A1h[2], A1h[3], bAh + aoff[1] + kadd);
            ldm_x4(A0l[0], A0l[1], A0l[2], A0l[3], bAl + aoff[0] + kadd);
            ldm_x4(A1l[0], A1l[1], A1l[2], A1l[3], bAl + aoff[1] + kadd);
#pragma unroll
            for (int nf = 0; nf < 4; nf++) {
                uint32_t bh[4], bl[4];
                ldm_x4(bh[0], bh[1], bh[2], bh[3], bBh + boff[nf] + kadd);
                ldm_x4(bl[0], bl[1], bl[2], bl[3], bBl + boff[nf] + kadd);
                mma_bf16(acc[0][nf * 2 + 0], A0h, bh[0], bh[1]);
                mma_bf16(acc[0][nf * 2 + 0], A0h, bl[0], bl[1]);
                mma_bf16(acc[0][nf * 2 + 0], A0l, bh[0], bh[1]);
                mma_bf16(acc[0][nf * 2 + 1], A0h, bh[2], bh[3]);
                mma_bf16(acc[0][nf * 2 + 1], A0h, bl[2], bl[3]);
                mma_bf16(acc[0][nf * 2 + 1], A0l, bh[2], bh[3]);
                mma_bf16(acc[1][nf * 2 + 0], A1h, bh[0], bh[1]);
                mma_bf16(acc[1][nf * 2 + 0], A1h, bl[0], bl[1]);
                mma_bf16(acc[1][nf * 2 + 0], A1l, bh[0], bh[1]);
                mma_bf16(acc[1][nf * 2 + 1], A1h, bh[2], bh[3]);
                mma_bf16(acc[1][nf * 2 + 1], A1h, bl[2], bl[3]);
                mma_bf16(acc[1][nf * 2 + 1], A1l, bh[2], bh[3]);
            }
        }
        if (c + 1 < nch) stageA(c + 1);
    }

    // epilogue: C[r, c] = (acc + bias[c]) * (dinv ? dinv[r] : 1)
    const int qr = lane >> 2;
    const int qc = (lane & 3) * 2;
#pragma unroll
    for (int mf = 0; mf < 2; mf++) {
        int rr0 = brow + wm * 32 + mf * 16 + qr;
        int rr1 = rr0 + 8;
        float dv0 = (rr0 < M) ? (dinv ? dinv[rr0] : 1.0f) : 0.f;
        float dv1 = (rr1 < M) ? (dinv ? dinv[rr1] : 1.0f) : 0.f;
#pragma unroll
        for (int nf = 0; nf < 8; nf++) {
            int cc = bcol + wn * 64 + nf * 8 + qc;
            float b0 = bias[cc], b1 = bias[cc + 1];
            if (rr0 < M)
                *(float2*)(C + (size_t)rr0 * HDIM + cc) =
                    make_float2((acc[mf][nf][0] + b0) * dv0,
                                (acc[mf][nf][1] + b1) * dv0);
            if (rr1 < M)
                *(float2*)(C + (size_t)rr1 * HDIM + cc) =
                    make_float2((acc[mf][nf][2] + b0) * dv1,
                                (acc[mf][nf][3] + b1) * dv1);
        }
    }
}

// ---------------- CSR aggregation + fused BN stats (2-pair index prefetch) --
__global__ __launch_bounds__(256)
void agg_kernel(const int* __restrict__ rowptr, const int* __restrict__ csr,
                const float* __restrict__ dinv, const float* __restrict__ tp,
                float* __restrict__ h, float* gsum, float* gsq) {
    __shared__ float s_sum[HDIM];
    __shared__ float s_sq[HDIM];
    int tid  = threadIdx.x;
    int lane = tid & 31;
    int warp = tid >> 5;
    int gw   = blockIdx.x * 8 + warp;
    int nw   = gridDim.x * 8;

    s_sum[tid] = 0.f;
    s_sq[tid]  = 0.f;

    float ssum[8], ssq[8];
#pragma unroll
    for (int i = 0; i < 8; i++) { ssum[i] = 0.f; ssq[i] = 0.f; }

    for (int v = gw; v < N_NODES; v += nw) {
        const float4* self = (const float4*)(tp + (size_t)v * HDIM);
        float4 a0 = self[lane];
        float4 a1 = self[lane + 32];
        int beg = rowptr[v], end = rowptr[v + 1];
        int e = beg;
        // two index pairs in flight
        int n0 = 0, n1 = 0, m0 = 0, m1 = 0;
        if (e + 1 < end) { n0 = csr[e]; n1 = csr[e + 1]; }
        if (e + 3 < end) { m0 = csr[e + 2]; m1 = csr[e + 3]; }
        while (e + 1 < end) {
            int s0 = n0, s1 = n1;
            n0 = m0; n1 = m1;
            int en = e + 2;
            if (en + 3 < end) { m0 = csr[en + 2]; m1 = csr[en + 3]; }
            const float4* r0 = (const float4*)(tp + (size_t)s0 * HDIM);
            const float4* r1 = (const float4*)(tp + (size_t)s1 * HDIM);
            float4 v00 = r0[lane], v01 = r0[lane + 32];
            float4 v10 = r1[lane], v11 = r1[lane + 32];
            a0.x += v00.x + v10.x; a0.y += v00.y + v10.y;
            a0.z += v00.z + v10.z; a0.w += v00.w + v10.w;
            a1.x += v01.x + v11.x; a1.y += v01.y + v11.y;
            a1.z += v01.z + v11.z; a1.w += v01.w + v11.w;
            e = en;
        }
        if (e < end) {
            int s0 = csr[e];
            const float4* r0 = (const float4*)(tp + (size_t)s0 * HDIM);
            float4 v00 = r0[lane], v01 = r0[lane + 32];
            a0.x += v00.x; a0.y += v00.y; a0.z += v00.z; a0.w += v00.w;
            a1.x += v01.x; a1.y += v01.y; a1.z += v01.z; a1.w += v01.w;
        }
        float dv = dinv[v];
        a0.x *= dv; a0.y *= dv; a0.z *= dv; a0.w *= dv;
        a1.x *= dv; a1.y *= dv; a1.z *= dv; a1.w *= dv;
        float4* hrow = (float4*)(h + (size_t)v * HDIM);
        hrow[lane]      = a0;
        hrow[lane + 32] = a1;
        ssum[0] += a0.x; ssum[1] += a0.y; ssum[2] += a0.z; ssum[3] += a0.w;
        ssum[4] += a1.x; ssum[5] += a1.y; ssum[6] += a1.z; ssum[7] += a1.w;
        ssq[0] += a0.x * a0.x; ssq[1] += a0.y * a0.y;
        ssq[2] += a0.z * a0.z; ssq[3] += a0.w * a0.w;
        ssq[4] += a1.x * a1.x; ssq[5] += a1.y * a1.y;
        ssq[6] += a1.z * a1.z; ssq[7] += a1.w * a1.w;
    }
    __syncthreads();
#pragma unroll
    for (int k = 0; k < 4; k++) {
        atomicAdd(&s_sum[lane * 4 + k], ssum[k]);
        atomicAdd(&s_sum[128 + lane * 4 + k], ssum[4 + k]);
        atomicAdd(&s_sq[lane * 4 + k], ssq[k]);
        atomicAdd(&s_sq[128 + lane * 4 + k], ssq[4 + k]);
    }
    __syncthreads();
    atomicAdd(&gsum[tid], s_sum[tid]);
    atomicAdd(&gsq[tid], s_sq[tid]);
}

// ---------------- output FC + fused combine + log-softmax -------------------
#define BM 128
#define BN 128
#define BK 16
__global__ __launch_bounds__(256, 2)
void out_gemm_kernel(const float* __restrict__ hist,
                     const float* __restrict__ sums, const float* __restrict__ sqs,
                     const float* __restrict__ gamma, const float* __restrict__ beta,
                     const float* __restrict__ w,
                     const float* __restrict__ B,
                     const float* __restrict__ bias, float* __restrict__ out,
                     int M) {
    const int Nc = C_OUT;
    const int K = HDIM;
    const size_t NH = (size_t)N_NODES * HDIM;
    __shared__ float As[2][BK][BM + 4];
    __shared__ float Bs[2][BK][BN];
    extern __shared__ float tbl[];
    float* tS  = tbl;          // [8][256]
    float* tSh = tbl + 2048;   // [8][256]
    float* tw  = tbl + 4096;   // [8]

    const int tid  = threadIdx.x;
    const int tRow = tid >> 4;
    const int tCol = tid & 15;
    const int brow = blockIdx.y * BM;
    const int am0 = tid >> 2;
    const int am1 = (tid + 256) >> 2;
    const int ak  = (tid & 3) * 4;
    const int arow0 = min(brow + am0, M - 1);
    const int arow1 = min(brow + am1, M - 1);
    const int bk0 = tid >> 5;
    const int bk1 = bk0 + 8;
    const int bnx = (tid & 31) * 4;
    const bool bok = (bnx + 3) < Nc;
    const int bcl  = bok ? bnx : 0;

    if (tid < 256) {
#pragma unroll
        for (int l = 0; l < L_LAYERS; l++) {
            float mu  = sums[l * HDIM + tid] * (1.0f / N_NODES);
            float var = sqs[l * HDIM + tid] * (1.0f / N_NODES) - mu * mu;
            float s = gamma[l * HDIM + tid] * rsqrtf(var + BN_EPS);
            tS[l * 256 + tid] = s;
            tSh[l * 256 + tid] = beta[l * HDIM + tid] - mu * s;
        }
    }
    if (tid < L_LAYERS) tw[tid] = w[tid];
    __syncthreads();

    auto combineA = [&](int row, int kc) -> float4 {
        float4 a = make_float4(0.f, 0.f, 0.f, 0.f);
#pragma unroll
        for (int l = 0; l < L_LAYERS; l++) {
            float4 v  = *(const float4*)(hist + (size_t)l * NH + (size_t)row * HDIM + kc);
            float4 s  = *(const float4*)(tS + l * 256 + kc);
            float4 sh = *(const float4*)(tSh + l * 256 + kc);
            float wl = tw[l];
            a.x = fmaf(wl, fmaxf(fmaf(v.x, s.x, sh.x), 0.f), a.x);
            a.y = fmaf(wl, fmaxf(fmaf(v.y, s.y, sh.y), 0.f), a.y);
            a.z = fmaf(wl, fmaxf(fmaf(v.z, s.z, sh.z), 0.f), a.z);
            a.w = fmaf(wl, fmaxf(fmaf(v.w, s.w, sh.w), 0.f), a.w);
        }
        return a;
    };

    unsigned long long acc[8][4];
#pragma unroll
    for (int i = 0; i < 8; i++)
#pragma unroll
        for (int j = 0; j < 4; j++) acc[i][j] = 0ull;

    float4 aR0, aR1, bR0, bR1;
    const float4 z4 = make_float4(0.f, 0.f, 0.f, 0.f);
    aR0 = combineA(arow0, ak);
    aR1 = combineA(arow1, ak);
    bR0 = bok ? *(const float4*)(B + (size_t)bk0 * Nc + bcl) : z4;
    bR1 = bok ? *(const float4*)(B + (size_t)bk1 * Nc + bcl) : z4;
    As[0][ak + 0][am0] = aR0.x; As[0][ak + 1][am0] = aR0.y;
    As[0][ak + 2][am0] = aR0.z; As[0][ak + 3][am0] = aR0.w;
    As[0][ak + 0][am1] = aR1.x; As[0][ak + 1][am1] = aR1.y;
    As[0][ak + 2][am1] = aR1.z; As[0][ak + 3][am1] = aR1.w;
    *(float4*)&Bs[0][bk0][bnx] = bR0;
    *(float4*)&Bs[0][bk1][bnx] = bR1;
    __syncthreads();

    const int nt = K / BK;
    for (int kt = 0; kt < nt; kt++) {
        const int buf = kt & 1;
        const int nxt = kt + 1;
        if (nxt < nt) {
            const int k0 = nxt * BK;
            aR0 = combineA(arow0, k0 + ak);
            aR1 = combineA(arow1, k0 + ak);
            bR0 = bok ? *(const float4*)(B + (size_t)(k0 + bk0) * Nc + bcl) : z4;
            bR1 = bok ? *(const float4*)(B + (size_t)(k0 + bk1) * Nc + bcl) : z4;
        }
#pragma unroll
        for (int k = 0; k < BK; k++) {
            float4 a0 = *(const float4*)&As[buf][k][tRow * 4];
            float4 a1 = *(const float4*)&As[buf][k][64 + tRow * 4];
            float4 b0 = *(const float4*)&Bs[buf][k][tCol * 4];
            float4 b1 = *(const float4*)&Bs[buf][k][64 + tCol * 4];
            unsigned long long bb[4] = {pk2(b0.x, b0.y), pk2(b0.z, b0.w),
                                        pk2(b1.x, b1.y), pk2(b1.z, b1.w)};
            float av[8] = {a0.x, a0.y, a0.z, a0.w, a1.x, a1.y, a1.z, a1.w};
#pragma unroll
            for (int i = 0; i < 8; i++) {
                unsigned long long ap = pk2(av[i], av[i]);
#pragma unroll
                for (int j = 0; j < 4; j++) ffma2(acc[i][j], ap, bb[j]);
            }
        }
        if (nxt < nt) {
            const int nb = nxt & 1;
            As[nb][ak + 0][am0] = aR0.x; As[nb][ak + 1][am0] = aR0.y;
            As[nb][ak + 2][am0] = aR0.z; As[nb][ak + 3][am0] = aR0.w;
            As[nb][ak + 0][am1] = aR1.x; As[nb][ak + 1][am1] = aR1.y;
            As[nb][ak + 2][am1] = aR1.z; As[nb][ak + 3][am1] = aR1.w;
            *(float4*)&Bs[nb][bk0][bnx] = bR0;
            *(float4*)&Bs[nb][bk1][bnx] = bR1;
        }
        __syncthreads();
    }

    // fused log-softmax epilogue
#pragma unroll
    for (int ih = 0; ih < 2; ih++) {
#pragma unroll
        for (int i = 0; i < 4; i++) {
            int r = brow + ih * 64 + tRow * 4 + i;
            float vals[8];
#pragma unroll
            for (int jh = 0; jh < 2; jh++) {
                float e0, e1, e2, e3;
                upk2(e0, e1, acc[ih * 4 + i][jh * 2 + 0]);
                upk2(e2, e3, acc[ih * 4 + i][jh * 2 + 1]);
                int c = jh * 64 + tCol * 4;
                vals[jh * 4 + 0] = (c + 0 < Nc) ? e0 + bias[c + 0] : -1e30f;
                vals[jh * 4 + 1] = (c + 1 < Nc) ? e1 + bias[c + 1] : -1e30f;
                vals[jh * 4 + 2] = (c + 2 < Nc) ? e2 + bias[c + 2] : -1e30f;
                vals[jh * 4 + 3] = (c + 3 < Nc) ? e3 + bias[c + 3] : -1e30f;
            }
            float m = vals[0];
#pragma unroll
            for (int j = 1; j < 8; j++) m = fmaxf(m, vals[j]);
#pragma unroll
            for (int off = 8; off >= 1; off >>= 1)
                m = fmaxf(m, __shfl_xor_sync(0xffffffffu, m, off));
            float s = 0.f;
#pragma unroll
            for (int j = 0; j < 8; j++) s += expf(vals[j] - m);
#pragma unroll
            for (int off = 8; off >= 1; off >>= 1)
                s += __shfl_xor_sync(0xffffffffu, s, off);
            float lse = m + logf(s);
            if (r < M) {
#pragma unroll
                for (int jh = 0; jh < 2; jh++) {
                    int c = jh * 64 + tCol * 4;
#pragma unroll
                    for (int j = 0; j < 4; j++)
                        if (c + j < Nc)
                            out[(size_t)r * Nc + c + j] = vals[jh * 4 + j] - lse;
                }
            }
        }
    }
}

// ---------------- host launcher ---------------------------------------------
extern "C" void kernel_launch(void* const* d_in, const int* in_sizes, int n_in,
                              void* d_out, int out_size) {
    const float* x       = (const float*)d_in[0];
    const int*   e1      = (const int*)  d_in[1];
    const int*   e2      = (const int*)  d_in[2];
    const float* in_W    = (const float*)d_in[3];
    const float* in_b    = (const float*)d_in[4];
    const float* convW   = (const float*)d_in[5];
    const float* convB   = (const float*)d_in[6];
    const float* bng     = (const float*)d_in[7];
    const float* bnb     = (const float*)d_in[8];
    const float* out_W   = (const float*)d_in[9];
    const float* out_b   = (const float*)d_in[10];
    const float* layer_w = (const float*)d_in[11];
    float* out = (float*)d_out;

    float *p_h0, *p_t, *p_hist, *p_dinv1, *p_dinv2, *p_sums, *p_sqs, *p_w;
    __nv_bfloat16 *p_wth, *p_wtl, *p_inwh, *p_inwl;
    int *p_cnt1, *p_cnt2, *p_part, *p_rp1, *p_rp2, *p_cur1, *p_cur2, *p_csr1, *p_csr2;
    cudaGetSymbolAddress((void**)&p_h0, g_h0);
    cudaGetSymbolAddress((void**)&p_t, g_t);
    cudaGetSymbolAddress((void**)&p_hist, g_hist);
    cudaGetSymbolAddress((void**)&p_wth, g_wth);
    cudaGetSymbolAddress((void**)&p_wtl, g_wtl);
    cudaGetSymbolAddress((void**)&p_inwh, g_inwh);
    cudaGetSymbolAddress((void**)&p_inwl, g_inwl);
    cudaGetSymbolAddress((void**)&p_dinv1, g_dinv1);
    cudaGetSymbolAddress((void**)&p_dinv2, g_dinv2);
    cudaGetSymbolAddress((void**)&p_sums, g_sums);
    cudaGetSymbolAddress((void**)&p_sqs, g_sqs);
    cudaGetSymbolAddress((void**)&p_w, g_w);
    cudaGetSymbolAddress((void**)&p_cnt1, g_cnt1);
    cudaGetSymbolAddress((void**)&p_cnt2, g_cnt2);
    cudaGetSymbolAddress((void**)&p_part, g_part);
    cudaGetSymbolAddress((void**)&p_rp1, g_rp1);
    cudaGetSymbolAddress((void**)&p_rp2, g_rp2);
    cudaGetSymbolAddress((void**)&p_cur1, g_cur1);
    cudaGetSymbolAddress((void**)&p_cur2, g_cur2);
    cudaGetSymbolAddress((void**)&p_csr1, g_csr1);
    cudaGetSymbolAddress((void**)&p_csr2, g_csr2);

    const int outSmem = (2048 + 2048 + 8) * sizeof(float);   // 16416 B dynamic
    cudaFuncSetAttribute(mma_gemm_kernel,
                         cudaFuncAttributeMaxDynamicSharedMemorySize, MG_SMEM);
    cudaFuncSetAttribute(out_gemm_kernel,
                         cudaFuncAttributeMaxDynamicSharedMemorySize, outSmem);

    const int nThr = 256;
    const int nbE2 = (E_EDGES / 2 + nThr - 1) / nThr;        // 2 edges per thread
    const int nbW  = (L_LAYERS * HDIM * HDIM + nThr - 1) / nThr;
    const dim3 outGrid(1, (N_NODES + BM - 1) / BM);
    const dim3 mmaGrid(2, (N_NODES + 127) / 128);
    const dim3 segGrid(NSEG, 2);
    const int aggBlocks = 1480;
    const size_t NH = (size_t)N_NODES * HDIM;

    prep_kernel<<<nbW, nThr>>>(convW, in_W, layer_w, p_wth, p_wtl,
                               p_inwh, p_inwl, p_sums, p_sqs, p_w,
                               p_cnt1, p_cnt2);

    // input FC on the tensor path: h0 = x @ in_W + in_b  (K=128, no BN/dinv)
    mma_gemm_kernel<<<mmaGrid, nThr, MG_SMEM>>>(
        x, F_INPUT, nullptr, nullptr, nullptr, nullptr, 0,
        p_inwh, p_inwl, in_b, nullptr, p_h0, N_NODES);

    hist2_kernel<<<nbE2, nThr>>>(e1 + E_EDGES, e2 + E_EDGES, p_cnt1, p_cnt2);
    partial2_kernel<<<segGrid, nThr>>>(p_cnt1, p_cnt2, p_part);
    scanemit2_kernel<<<segGrid, nThr>>>(p_cnt1, p_cnt2, p_part, p_rp1, p_rp2,
                                        p_dinv1, p_dinv2, p_cur1, p_cur2);
    fill2_kernel<<<nbE2, nThr>>>(e1, e2, p_cur1, p_cur2, p_csr1, p_csr2);

    for (int l = 0; l < L_LAYERS; l++) {
        const int*   rp   = (l < L_LAYERS / 2) ? p_rp1 : p_rp2;
        const int*   csr  = (l < L_LAYERS / 2) ? p_csr1 : p_csr2;
        const float* dinv = (l < L_LAYERS / 2) ? p_dinv1 : p_dinv2;
        const float* Hin  = (l == 0) ? p_h0 : p_hist + (size_t)(l - 1) * NH;
        const float* bs   = (l == 0) ? p_sums : p_sums + (l - 1) * HDIM;
        const float* bq   = (l == 0) ? p_sqs  : p_sqs + (l - 1) * HDIM;
        const float* bg   = (l == 0) ? bng : bng + (l - 1) * HDIM;
        const float* bb   = (l == 0) ? bnb : bnb + (l - 1) * HDIM;

        mma_gemm_kernel<<<mmaGrid, nThr, MG_SMEM>>>(
            Hin, HDIM, bs, bq, bg, bb, (l > 0) ? 1 : 0,
            p_wth + (size_t)l * HDIM * HDIM, p_wtl + (size_t)l * HDIM * HDIM,
            convB + l * HDIM, dinv, p_t, N_NODES);
        agg_kernel<<<aggBlocks, nThr>>>(rp, csr, dinv, p_t,
                                        p_hist + (size_t)l * NH,
                                        p_sums + l * HDIM, p_sqs + l * HDIM);
    }

    out_gemm_kernel<<<outGrid, nThr, outSmem>>>(
        p_hist, p_sums, p_sqs, bng, bnb, p_w, out_W, out_b, out, N_NODES);
}